// round 1
// baseline (speedup 1.0000x reference)
#include <cuda_runtime.h>
#include <cuda_bf16.h>
#include <math.h>

// ---------------------------------------------------------------------------
// Problem constants (fixed by the dataset)
// ---------------------------------------------------------------------------
#define NMAX   20000
#define EMAX   320000
#define ETOTMX (EMAX + NMAX)
#define GMAX   32

// ---------------------------------------------------------------------------
// Scratch (device globals; no allocations allowed anywhere)
// ---------------------------------------------------------------------------
__device__ float    g_h   [NMAX * 768];    // proj output
__device__ float    g_hw  [NMAX * 1024];   // GAT linear output (per layer, reused)
__device__ float    g_agg [NMAX * 1024];   // aggregation accumulator (reused)
__device__ float    g_x1  [NMAX * 1024];
__device__ float    g_x2  [NMAX * 1024];
__device__ float    g_x3  [NMAX * 256];
__device__ float    g_es  [NMAX * 4];
__device__ float    g_ed  [NMAX * 4];
__device__ unsigned g_smax[NMAX * 4];
__device__ float    g_den [NMAX * 4];
__device__ float    g_elog[ETOTMX * 4];    // logits, then exp() in place
__device__ float    g_psum[GMAX * 256];
__device__ unsigned g_pmax[GMAX * 256];
__device__ float    g_pcnt[GMAX];

// ---------------------------------------------------------------------------
// Helpers
// ---------------------------------------------------------------------------
__device__ __forceinline__ unsigned enc_f(float f) {
    unsigned u = __float_as_uint(f);
    return (u & 0x80000000u) ? ~u : (u | 0x80000000u);
}
__device__ __forceinline__ float dec_f(unsigned k) {
    unsigned u = (k & 0x80000000u) ? (k & 0x7fffffffu) : ~k;
    return __uint_as_float(u);
}
__device__ __forceinline__ float warpSum(float v) {
    #pragma unroll
    for (int o = 16; o > 0; o >>= 1) v += __shfl_xor_sync(0xffffffffu, v, o);
    return v;
}
// Block reduction; sh must have >= blockDim/32 floats. Safe for repeated use.
__device__ __forceinline__ float blockSum(float v, float* sh) {
    int lane = threadIdx.x & 31, w = threadIdx.x >> 5;
    int nw = blockDim.x >> 5;
    v = warpSum(v);
    __syncthreads();
    if (lane == 0) sh[w] = v;
    __syncthreads();
    float r = (threadIdx.x < nw) ? sh[threadIdx.x] : 0.0f;
    if (w == 0) {
        r = warpSum(r);
        if (lane == 0) sh[0] = r;
    }
    __syncthreads();
    return sh[0];
}
__device__ __forceinline__ float eluf(float x) { return x > 0.0f ? x : expm1f(x); }

// ---------------------------------------------------------------------------
// GEMM: C[M,N] = A[M,K] @ B[K,N], row-major.
// 128x128 tile, BK=8, 256 threads, 8x8 per thread. Requires N%128==0, K%8==0.
// EPI: 0 = none, 1 = +bias, 2 = +bias then ELU.
// ---------------------------------------------------------------------------
template<int EPI>
__global__ __launch_bounds__(256)
void sgemm128(const float* __restrict__ A, const float* __restrict__ B,
              const float* __restrict__ bias, float* __restrict__ C,
              int M, int N, int K)
{
    __shared__ float As[8][128];
    __shared__ float Bs[8][128];

    int tid = threadIdx.x;
    int tx = tid & 15, ty = tid >> 4;
    int row0 = blockIdx.y * 128;
    int col0 = blockIdx.x * 128;

    float acc[8][8];
    #pragma unroll
    for (int i = 0; i < 8; i++)
        #pragma unroll
        for (int j = 0; j < 8; j++) acc[i][j] = 0.0f;

    int arow = tid >> 1;          // 0..127
    int acol = (tid & 1) << 2;    // 0 or 4
    int brow = tid >> 5;          // 0..7
    int bcol = (tid & 31) << 2;   // 0..124

    for (int k0 = 0; k0 < K; k0 += 8) {
        int gm = row0 + arow;
        float4 av = make_float4(0.f, 0.f, 0.f, 0.f);
        if (gm < M) av = *(const float4*)(A + (size_t)gm * K + k0 + acol);
        As[acol + 0][arow] = av.x;
        As[acol + 1][arow] = av.y;
        As[acol + 2][arow] = av.z;
        As[acol + 3][arow] = av.w;
        float4 bv = *(const float4*)(B + (size_t)(k0 + brow) * N + col0 + bcol);
        *(float4*)(&Bs[brow][bcol]) = bv;
        __syncthreads();

        #pragma unroll
        for (int k = 0; k < 8; k++) {
            float4 a0 = *(const float4*)(&As[k][ty * 8]);
            float4 a1 = *(const float4*)(&As[k][ty * 8 + 4]);
            float4 b0 = *(const float4*)(&Bs[k][tx * 8]);
            float4 b1 = *(const float4*)(&Bs[k][tx * 8 + 4]);
            float a[8] = {a0.x, a0.y, a0.z, a0.w, a1.x, a1.y, a1.z, a1.w};
            float b[8] = {b0.x, b0.y, b0.z, b0.w, b1.x, b1.y, b1.z, b1.w};
            #pragma unroll
            for (int i = 0; i < 8; i++)
                #pragma unroll
                for (int j = 0; j < 8; j++)
                    acc[i][j] = fmaf(a[i], b[j], acc[i][j]);
        }
        __syncthreads();
    }

    #pragma unroll
    for (int i = 0; i < 8; i++) {
        int r = row0 + ty * 8 + i;
        if (r >= M) break;
        #pragma unroll
        for (int j = 0; j < 8; j++) {
            int c = col0 + tx * 8 + j;
            float v = acc[i][j];
            if (EPI >= 1) v += bias[c];
            if (EPI == 2) v = eluf(v);
            C[(size_t)r * N + c] = v;
        }
    }
}

// ---------------------------------------------------------------------------
// Attention scores: es[n,h] = sum_c hw[n,h,c]*a_src[h,c]; ed likewise.
// One warp per (node, head).
// ---------------------------------------------------------------------------
__global__ void attn_scores(const float* __restrict__ hw,
                            const float* __restrict__ a_src,
                            const float* __restrict__ a_dst,
                            float* __restrict__ es, float* __restrict__ ed,
                            int n, int H, int C)
{
    int gw = (blockIdx.x * blockDim.x + threadIdx.x) >> 5;
    int lane = threadIdx.x & 31;
    int node = gw / H, h = gw % H;
    if (node >= n) return;
    const float* row = hw + (size_t)node * H * C + h * C;
    const float* as = a_src + h * C;
    const float* ad = a_dst + h * C;
    float ss = 0.f, sd = 0.f;
    for (int c = lane; c < C; c += 32) {
        float v = row[c];
        ss = fmaf(v, as[c], ss);
        sd = fmaf(v, ad[c], sd);
    }
    ss = warpSum(ss);
    sd = warpSum(sd);
    if (lane == 0) { es[node * H + h] = ss; ed[node * H + h] = sd; }
}

// ---------------------------------------------------------------------------
// Edge pass 1: logits + segment max (encoded-uint atomicMax).
// ---------------------------------------------------------------------------
template<int H>
__global__ void edge_logits(const float* __restrict__ es, const float* __restrict__ ed,
                            const int* __restrict__ ei, float* __restrict__ elog,
                            unsigned* __restrict__ smax, int E, int Etot)
{
    int t = blockIdx.x * blockDim.x + threadIdx.x;
    if (t >= Etot * H) return;
    int e = t / H, h = t - e * H;
    int s, d;
    if (e < E) { s = ei[e]; d = ei[E + e]; } else { s = d = e - E; }
    float v = es[s * H + h] + ed[d * H + h];
    v = v > 0.0f ? v : 0.2f * v;           // leaky_relu 0.2
    elog[t] = v;
    atomicMax(&smax[d * H + h], enc_f(v));
}

// ---------------------------------------------------------------------------
// Edge pass 2: exp(logit - segmax) in place + denominator segment-sum.
// ---------------------------------------------------------------------------
template<int H>
__global__ void edge_exp(float* __restrict__ elog, const unsigned* __restrict__ smax,
                         float* __restrict__ den, const int* __restrict__ ei,
                         int E, int Etot)
{
    int t = blockIdx.x * blockDim.x + threadIdx.x;
    if (t >= Etot * H) return;
    int e = t / H, h = t - e * H;
    int d = (e < E) ? ei[E + e] : e - E;
    float m = dec_f(smax[d * H + h]);
    float ex = expf(elog[t] - m);
    elog[t] = ex;
    atomicAdd(&den[d * H + h], ex);
}

// ---------------------------------------------------------------------------
// Edge pass 3: agg[dst] += hw[src] * alpha.  One block per edge, F/4 threads.
// ---------------------------------------------------------------------------
template<int F, int H>
__global__ void scatter_edges(const float* __restrict__ hw, const float* __restrict__ ex,
                              const float* __restrict__ den, const int* __restrict__ ei,
                              float* __restrict__ agg, int E, int Etot)
{
    int e = blockIdx.x;
    int s, d;
    if (e < E) { s = ei[e]; d = ei[E + e]; } else { s = d = e - E; }
    __shared__ float al[H];
    if (threadIdx.x < H)
        al[threadIdx.x] = ex[(size_t)e * H + threadIdx.x] /
                          (den[(size_t)d * H + threadIdx.x] + 1e-16f);
    __syncthreads();
    constexpr int C = F / H;
    int c4 = threadIdx.x * 4;
    float4 v = *(const float4*)(hw + (size_t)s * F + c4);
    float a = al[c4 / C];
    float* o = agg + (size_t)d * F + c4;
    atomicAdd(o + 0, v.x * a);
    atomicAdd(o + 1, v.y * a);
    atomicAdd(o + 2, v.z * a);
    atomicAdd(o + 3, v.w * a);
}

// ---------------------------------------------------------------------------
// bias + LayerNorm + ELU (+ optional residual, added AFTER elu).
// One block (256 threads) per node.
// ---------------------------------------------------------------------------
template<int F, bool RES>
__global__ __launch_bounds__(256)
void ln_elu(const float* __restrict__ agg, const float* __restrict__ bias,
            const float* __restrict__ gam, const float* __restrict__ bet,
            const float* __restrict__ res, float* __restrict__ out)
{
    constexpr int T = 256, P = F / T;
    int node = blockIdx.x, tid = threadIdx.x;
    __shared__ float sh[8];
    const float* row = agg + (size_t)node * F;
    float v[P];
    float s = 0.f;
    #pragma unroll
    for (int i = 0; i < P; i++) {
        int c = tid + i * T;
        v[i] = row[c] + bias[c];
        s += v[i];
    }
    s = blockSum(s, sh);
    float mu = s * (1.0f / F);
    float q = 0.f;
    #pragma unroll
    for (int i = 0; i < P; i++) { float dd = v[i] - mu; q += dd * dd; }
    q = blockSum(q, sh);
    float inv = rsqrtf(q * (1.0f / F) + 1e-5f);
    #pragma unroll
    for (int i = 0; i < P; i++) {
        int c = tid + i * T;
        float y = (v[i] - mu) * inv * gam[c] + bet[c];
        y = eluf(y);
        if (RES) y += res[(size_t)node * F + c];
        out[(size_t)node * F + c] = y;
    }
}

// ---------------------------------------------------------------------------
// Graph pooling
// ---------------------------------------------------------------------------
__global__ void pool_cnt(const int* __restrict__ batch, float* __restrict__ pcnt, int n)
{
    int t = blockIdx.x * blockDim.x + threadIdx.x;
    if (t < n) atomicAdd(&pcnt[batch[t]], 1.0f);
}

__global__ void pool_feat(const float* __restrict__ x3, const int* __restrict__ batch,
                          float* __restrict__ psum, unsigned* __restrict__ pmax, int n)
{
    int t = blockIdx.x * blockDim.x + threadIdx.x;
    if (t >= n * 256) return;
    int node = t >> 8, c = t & 255;
    int g = batch[node];
    float v = x3[t];
    atomicAdd(&psum[g * 256 + c], v);
    atomicMax(&pmax[g * 256 + c], enc_f(v));
}

// ---------------------------------------------------------------------------
// Classifier head: out[g] = relu(pooled @ W1 + b1) @ W2 + b2
// pooled[g] = [mean(256) | max(256) | sum(256)].  32 blocks x 128 threads.
// ---------------------------------------------------------------------------
__global__ __launch_bounds__(128)
void classifier(const float* __restrict__ psum, const unsigned* __restrict__ pmax,
                const float* __restrict__ pcnt,
                const float* __restrict__ w1, const float* __restrict__ b1,
                const float* __restrict__ w2, const float* __restrict__ b2,
                float* __restrict__ out)
{
    int g = blockIdx.x;
    int tid = threadIdx.x;
    __shared__ float p[768];
    __shared__ float r4[4];
    float cnt = fmaxf(pcnt[g], 1.0f);
    for (int i = tid; i < 768; i += 128) {
        float val;
        if (i < 256)      val = psum[g * 256 + i] / cnt;
        else if (i < 512) val = dec_f(pmax[g * 256 + (i - 256)]);
        else              val = psum[g * 256 + (i - 512)];
        p[i] = val;
    }
    __syncthreads();
    float acc = b1[tid];
    for (int k = 0; k < 768; k++) acc = fmaf(p[k], w1[k * 128 + tid], acc);
    float hv = fmaxf(acc, 0.0f) * w2[tid];
    hv = warpSum(hv);
    if ((tid & 31) == 0) r4[tid >> 5] = hv;
    __syncthreads();
    if (tid == 0) out[g] = r4[0] + r4[1] + r4[2] + r4[3] + b2[0];
}

// ---------------------------------------------------------------------------
// Launcher
// ---------------------------------------------------------------------------
extern "C" void kernel_launch(void* const* d_in, const int* in_sizes, int n_in,
                              void* d_out, int out_size)
{
    const float* x        = (const float*)d_in[0];
    const int*   ei       = (const int*)  d_in[1];
    const int*   batch    = (const int*)  d_in[2];
    const float* proj_w   = (const float*)d_in[3];
    const float* proj_b   = (const float*)d_in[4];
    const float* gat1_w   = (const float*)d_in[5];
    const float* att1_src = (const float*)d_in[6];
    const float* att1_dst = (const float*)d_in[7];
    const float* gat1_b   = (const float*)d_in[8];
    const float* ln1_g    = (const float*)d_in[9];
    const float* ln1_b    = (const float*)d_in[10];
    const float* gat2_w   = (const float*)d_in[11];
    const float* att2_src = (const float*)d_in[12];
    const float* att2_dst = (const float*)d_in[13];
    const float* gat2_b   = (const float*)d_in[14];
    const float* ln2_g    = (const float*)d_in[15];
    const float* ln2_b    = (const float*)d_in[16];
    const float* gat3_w   = (const float*)d_in[17];
    const float* att3_src = (const float*)d_in[18];
    const float* att3_dst = (const float*)d_in[19];
    const float* gat3_b   = (const float*)d_in[20];
    const float* ln3_g    = (const float*)d_in[21];
    const float* ln3_b    = (const float*)d_in[22];
    const float* cls1_w   = (const float*)d_in[23];
    const float* cls1_b   = (const float*)d_in[24];
    const float* cls2_w   = (const float*)d_in[25];
    const float* cls2_b   = (const float*)d_in[26];
    float* out = (float*)d_out;

    int n    = in_sizes[2];       // 20000
    int E    = in_sizes[1] / 2;   // 320000
    int Etot = E + n;

    float    *h_, *hw, *agg, *x1, *x2, *x3, *es_, *ed_, *den, *elog, *psum, *pcnt;
    unsigned *smax, *pmax;
    cudaGetSymbolAddress((void**)&h_,   g_h);
    cudaGetSymbolAddress((void**)&hw,   g_hw);
    cudaGetSymbolAddress((void**)&agg,  g_agg);
    cudaGetSymbolAddress((void**)&x1,   g_x1);
    cudaGetSymbolAddress((void**)&x2,   g_x2);
    cudaGetSymbolAddress((void**)&x3,   g_x3);
    cudaGetSymbolAddress((void**)&es_,  g_es);
    cudaGetSymbolAddress((void**)&ed_,  g_ed);
    cudaGetSymbolAddress((void**)&smax, g_smax);
    cudaGetSymbolAddress((void**)&den,  g_den);
    cudaGetSymbolAddress((void**)&elog, g_elog);
    cudaGetSymbolAddress((void**)&psum, g_psum);
    cudaGetSymbolAddress((void**)&pmax, g_pmax);
    cudaGetSymbolAddress((void**)&pcnt, g_pcnt);

    int mBlocks = (n + 127) / 128;
    int eThreads4 = (Etot * 4 + 255) / 256;
    int eThreads1 = (Etot + 255) / 256;

    // h = elu(x @ proj_w + proj_b)
    sgemm128<2><<<dim3(768 / 128, mBlocks), 256>>>(x, proj_w, proj_b, h_, n, 768, 768);

    // ---------------- GAT layer 1 (H=4, C=256, F=1024) ----------------
    sgemm128<0><<<dim3(1024 / 128, mBlocks), 256>>>(h_, gat1_w, nullptr, hw, n, 1024, 768);
    attn_scores<<<(n * 4) / 8, 256>>>(hw, att1_src, att1_dst, es_, ed_, n, 4, 256);
    cudaMemsetAsync(smax, 0, (size_t)n * 4 * sizeof(unsigned), 0);
    cudaMemsetAsync(den,  0, (size_t)n * 4 * sizeof(float), 0);
    cudaMemsetAsync(agg,  0, (size_t)n * 1024 * sizeof(float), 0);
    edge_logits<4><<<eThreads4, 256>>>(es_, ed_, ei, elog, smax, E, Etot);
    edge_exp<4><<<eThreads4, 256>>>(elog, smax, den, ei, E, Etot);
    scatter_edges<1024, 4><<<Etot, 256>>>(hw, elog, den, ei, agg, E, Etot);
    ln_elu<1024, false><<<n, 256>>>(agg, gat1_b, ln1_g, ln1_b, nullptr, x1);

    // ---------------- GAT layer 2 (H=4, C=256, F=1024, residual) -------
    sgemm128<0><<<dim3(1024 / 128, mBlocks), 256>>>(x1, gat2_w, nullptr, hw, n, 1024, 1024);
    attn_scores<<<(n * 4) / 8, 256>>>(hw, att2_src, att2_dst, es_, ed_, n, 4, 256);
    cudaMemsetAsync(smax, 0, (size_t)n * 4 * sizeof(unsigned), 0);
    cudaMemsetAsync(den,  0, (size_t)n * 4 * sizeof(float), 0);
    cudaMemsetAsync(agg,  0, (size_t)n * 1024 * sizeof(float), 0);
    edge_logits<4><<<eThreads4, 256>>>(es_, ed_, ei, elog, smax, E, Etot);
    edge_exp<4><<<eThreads4, 256>>>(elog, smax, den, ei, E, Etot);
    scatter_edges<1024, 4><<<Etot, 256>>>(hw, elog, den, ei, agg, E, Etot);
    ln_elu<1024, true><<<n, 256>>>(agg, gat2_b, ln2_g, ln2_b, x1, x2);

    // ---------------- GAT layer 3 (H=1, C=256, F=256) -------------------
    sgemm128<0><<<dim3(256 / 128, mBlocks), 256>>>(x2, gat3_w, nullptr, hw, n, 256, 1024);
    attn_scores<<<(n + 7) / 8, 256>>>(hw, att3_src, att3_dst, es_, ed_, n, 1, 256);
    cudaMemsetAsync(smax, 0, (size_t)n * sizeof(unsigned), 0);
    cudaMemsetAsync(den,  0, (size_t)n * sizeof(float), 0);
    cudaMemsetAsync(agg,  0, (size_t)n * 256 * sizeof(float), 0);
    edge_logits<1><<<eThreads1, 256>>>(es_, ed_, ei, elog, smax, E, Etot);
    edge_exp<1><<<eThreads1, 256>>>(elog, smax, den, ei, E, Etot);
    scatter_edges<256, 1><<<Etot, 64>>>(hw, elog, den, ei, agg, E, Etot);
    ln_elu<256, false><<<n, 256>>>(agg, gat3_b, ln3_g, ln3_b, nullptr, x3);

    // ---------------- Pooling + classifier ------------------------------
    cudaMemsetAsync(psum, 0, (size_t)GMAX * 256 * sizeof(float), 0);
    cudaMemsetAsync(pmax, 0, (size_t)GMAX * 256 * sizeof(unsigned), 0);
    cudaMemsetAsync(pcnt, 0, (size_t)GMAX * sizeof(float), 0);
    pool_cnt<<<(n + 255) / 256, 256>>>(batch, pcnt, n);
    pool_feat<<<(n * 256 + 255) / 256, 256>>>(x3, batch, psum, pmax, n);
    classifier<<<GMAX, 128>>>(psum, pmax, pcnt, cls1_w, cls1_b, cls2_w, cls2_b, out);
}

// round 2
// speedup vs baseline: 1.1123x; 1.1123x over previous
#include <cuda_runtime.h>
#include <cuda_bf16.h>
#include <math.h>

// ---------------------------------------------------------------------------
// Problem constants (fixed by the dataset)
// ---------------------------------------------------------------------------
#define NMAX   20000
#define EMAX   320000
#define ETOTMX (EMAX + NMAX)
#define GMAX   32

// ---------------------------------------------------------------------------
// Scratch (device globals; no allocations allowed anywhere)
// ---------------------------------------------------------------------------
__device__ float    g_h   [NMAX * 768];    // proj output
__device__ float    g_hw  [NMAX * 1024];   // GAT linear output (per layer, reused)
__device__ float    g_agg [NMAX * 1024];   // aggregation accumulator (reused)
__device__ float    g_x1  [NMAX * 1024];
__device__ float    g_x2  [NMAX * 1024];
__device__ float    g_x3  [NMAX * 256];
__device__ float    g_es  [NMAX * 4];
__device__ float    g_ed  [NMAX * 4];
__device__ unsigned g_smax[NMAX * 4];
__device__ float    g_den [NMAX * 4];
__device__ float    g_elog[ETOTMX * 4];    // logits, then exp() in place
__device__ float    g_psum[GMAX * 256];
__device__ unsigned g_pmax[GMAX * 256];
__device__ float    g_pcnt[GMAX];

// ---------------------------------------------------------------------------
// Helpers
// ---------------------------------------------------------------------------
__device__ __forceinline__ unsigned enc_f(float f) {
    unsigned u = __float_as_uint(f);
    return (u & 0x80000000u) ? ~u : (u | 0x80000000u);
}
__device__ __forceinline__ float dec_f(unsigned k) {
    unsigned u = (k & 0x80000000u) ? (k & 0x7fffffffu) : ~k;
    return __uint_as_float(u);
}
__device__ __forceinline__ float warpSum(float v) {
    #pragma unroll
    for (int o = 16; o > 0; o >>= 1) v += __shfl_xor_sync(0xffffffffu, v, o);
    return v;
}
__device__ __forceinline__ float blockSum(float v, float* sh) {
    int lane = threadIdx.x & 31, w = threadIdx.x >> 5;
    int nw = blockDim.x >> 5;
    v = warpSum(v);
    __syncthreads();
    if (lane == 0) sh[w] = v;
    __syncthreads();
    float r = (threadIdx.x < nw) ? sh[threadIdx.x] : 0.0f;
    if (w == 0) {
        r = warpSum(r);
        if (lane == 0) sh[0] = r;
    }
    __syncthreads();
    return sh[0];
}
__device__ __forceinline__ float eluf(float x) { return x > 0.0f ? x : expm1f(x); }

// Packed f32x2 primitives (sm_103a FFMA2 path — ptxas won't auto-fuse)
__device__ __forceinline__ unsigned long long dupf(float a) {
    unsigned long long r;
    asm("mov.b64 %0, {%1, %1};" : "=l"(r) : "f"(a));
    return r;
}
__device__ __forceinline__ void ffma2(unsigned long long& acc,
                                      unsigned long long a, unsigned long long b) {
    asm("fma.rn.f32x2 %0, %1, %2, %0;" : "+l"(acc) : "l"(a), "l"(b));
}
__device__ __forceinline__ float2 unpk(unsigned long long v) {
    float lo, hi;
    asm("mov.b64 {%0, %1}, %2;" : "=f"(lo), "=f"(hi) : "l"(v));
    return make_float2(lo, hi);
}

// ---------------------------------------------------------------------------
// GEMM: C[M,N] = A[M,K] @ B[K,N], row-major. FFMA2-packed fp32.
// 128x128 tile, BK=16, 256 threads, 8x8 per thread (as 8x4 packed pairs).
// Double-buffered smem, single sync per chunk. Requires N%128==0, K%16==0.
// EPI: 0 = none, 1 = +bias, 2 = +bias then ELU.
// ---------------------------------------------------------------------------
template<int EPI>
__global__ __launch_bounds__(256, 2)
void sgemm_f32x2(const float* __restrict__ A, const float* __restrict__ B,
                 const float* __restrict__ bias, float* __restrict__ C,
                 int M, int N, int K)
{
    __shared__ __align__(16) float As[2][16][128];
    __shared__ __align__(16) float Bs[2][16][128];

    const int tid = threadIdx.x;
    const int tx = tid & 15, ty = tid >> 4;
    const int row0 = blockIdx.y * 128, col0 = blockIdx.x * 128;

    unsigned long long acc[8][4];
    #pragma unroll
    for (int i = 0; i < 8; i++)
        #pragma unroll
        for (int j = 0; j < 4; j++) acc[i][j] = 0ull;

    // A-load mapping: row = tid>>1, k-offset = (tid&1)*8 (two float4)
    const int arow = tid >> 1, akoff = (tid & 1) * 8;
    const bool avalid = (row0 + arow) < M;
    const float* Abase = A + (size_t)(row0 + arow) * K + akoff;
    // B-load mapping: two float4s: f = tid and tid+256; row = f>>5, col4 = f&31
    const float* Bbase0 = B + (size_t)(tid >> 5) * N + col0 + (tid & 31) * 4;
    const float* Bbase1 = B + (size_t)((tid + 256) >> 5) * N + col0 + (tid & 31) * 4;
    const int nk = K >> 4;

    float4 pa0, pa1, pb0, pb1;
    // prefetch chunk 0
    pa0 = avalid ? *(const float4*)(Abase + 0) : make_float4(0.f, 0.f, 0.f, 0.f);
    pa1 = avalid ? *(const float4*)(Abase + 4) : make_float4(0.f, 0.f, 0.f, 0.f);
    pb0 = *(const float4*)(Bbase0);
    pb1 = *(const float4*)(Bbase1);

    int buf = 0;
    // store chunk 0
    As[buf][akoff + 0][arow] = pa0.x; As[buf][akoff + 1][arow] = pa0.y;
    As[buf][akoff + 2][arow] = pa0.z; As[buf][akoff + 3][arow] = pa0.w;
    As[buf][akoff + 4][arow] = pa1.x; As[buf][akoff + 5][arow] = pa1.y;
    As[buf][akoff + 6][arow] = pa1.z; As[buf][akoff + 7][arow] = pa1.w;
    *(float4*)&Bs[buf][tid >> 5][(tid & 31) * 4] = pb0;
    *(float4*)&Bs[buf][(tid + 256) >> 5][(tid & 31) * 4] = pb1;
    __syncthreads();

    for (int ch = 0; ch < nk; ch++) {
        const bool has_next = (ch + 1) < nk;
        if (has_next) {
            const float* Ap = Abase + (size_t)(ch + 1) * 16;
            pa0 = avalid ? *(const float4*)(Ap + 0) : make_float4(0.f, 0.f, 0.f, 0.f);
            pa1 = avalid ? *(const float4*)(Ap + 4) : make_float4(0.f, 0.f, 0.f, 0.f);
            const float* Bp = B + (size_t)(ch + 1) * 16 * N;
            pb0 = *(const float4*)(Bbase0 + (size_t)(ch + 1) * 16 * N);
            pb1 = *(const float4*)(Bbase1 + (size_t)(ch + 1) * 16 * N);
            (void)Bp;
        }
        // compute on current buffer
        #pragma unroll
        for (int k = 0; k < 16; k++) {
            float4 a0 = *(const float4*)&As[buf][k][ty * 8];
            float4 a1 = *(const float4*)&As[buf][k][ty * 8 + 4];
            ulonglong2 b01 = *(const ulonglong2*)&Bs[buf][k][tx * 8];
            ulonglong2 b23 = *(const ulonglong2*)&Bs[buf][k][tx * 8 + 4];
            float av[8] = {a0.x, a0.y, a0.z, a0.w, a1.x, a1.y, a1.z, a1.w};
            #pragma unroll
            for (int i = 0; i < 8; i++) {
                unsigned long long ad = dupf(av[i]);
                ffma2(acc[i][0], ad, b01.x);
                ffma2(acc[i][1], ad, b01.y);
                ffma2(acc[i][2], ad, b23.x);
                ffma2(acc[i][3], ad, b23.y);
            }
        }
        if (has_next) {
            int nb = buf ^ 1;
            As[nb][akoff + 0][arow] = pa0.x; As[nb][akoff + 1][arow] = pa0.y;
            As[nb][akoff + 2][arow] = pa0.z; As[nb][akoff + 3][arow] = pa0.w;
            As[nb][akoff + 4][arow] = pa1.x; As[nb][akoff + 5][arow] = pa1.y;
            As[nb][akoff + 6][arow] = pa1.z; As[nb][akoff + 7][arow] = pa1.w;
            *(float4*)&Bs[nb][tid >> 5][(tid & 31) * 4] = pb0;
            *(float4*)&Bs[nb][(tid + 256) >> 5][(tid & 31) * 4] = pb1;
        }
        __syncthreads();
        buf ^= 1;
    }

    // epilogue
    #pragma unroll
    for (int i = 0; i < 8; i++) {
        int r = row0 + ty * 8 + i;
        if (r >= M) break;
        float o[8];
        #pragma unroll
        for (int j = 0; j < 4; j++) {
            float2 p = unpk(acc[i][j]);
            o[2 * j] = p.x; o[2 * j + 1] = p.y;
        }
        int c = col0 + tx * 8;
        #pragma unroll
        for (int j = 0; j < 8; j++) {
            if (EPI >= 1) o[j] += bias[c + j];
            if (EPI == 2) o[j] = eluf(o[j]);
        }
        float* Cp = C + (size_t)r * N + c;
        *(float4*)(Cp)     = make_float4(o[0], o[1], o[2], o[3]);
        *(float4*)(Cp + 4) = make_float4(o[4], o[5], o[6], o[7]);
    }
}

// ---------------------------------------------------------------------------
// Attention scores: es[n,h] = sum_c hw[n,h,c]*a_src[h,c]; ed likewise.
// One warp per (node, head).
// ---------------------------------------------------------------------------
__global__ void attn_scores(const float* __restrict__ hw,
                            const float* __restrict__ a_src,
                            const float* __restrict__ a_dst,
                            float* __restrict__ es, float* __restrict__ ed,
                            int n, int H, int C)
{
    int gw = (blockIdx.x * blockDim.x + threadIdx.x) >> 5;
    int lane = threadIdx.x & 31;
    int node = gw / H, h = gw % H;
    if (node >= n) return;
    const float* row = hw + (size_t)node * H * C + h * C;
    const float* as = a_src + h * C;
    const float* ad = a_dst + h * C;
    float ss = 0.f, sd = 0.f;
    for (int c = lane; c < C; c += 32) {
        float v = row[c];
        ss = fmaf(v, as[c], ss);
        sd = fmaf(v, ad[c], sd);
    }
    ss = warpSum(ss);
    sd = warpSum(sd);
    if (lane == 0) { es[node * H + h] = ss; ed[node * H + h] = sd; }
}

// ---------------------------------------------------------------------------
// Edge pass 1: logits + segment max (encoded-uint atomicMax).
// ---------------------------------------------------------------------------
template<int H>
__global__ void edge_logits(const float* __restrict__ es, const float* __restrict__ ed,
                            const int* __restrict__ ei, float* __restrict__ elog,
                            unsigned* __restrict__ smax, int E, int Etot)
{
    int t = blockIdx.x * blockDim.x + threadIdx.x;
    if (t >= Etot * H) return;
    int e = t / H, h = t - e * H;
    int s, d;
    if (e < E) { s = ei[e]; d = ei[E + e]; } else { s = d = e - E; }
    float v = es[s * H + h] + ed[d * H + h];
    v = v > 0.0f ? v : 0.2f * v;           // leaky_relu 0.2
    elog[t] = v;
    atomicMax(&smax[d * H + h], enc_f(v));
}

// ---------------------------------------------------------------------------
// Edge pass 2: exp(logit - segmax) in place + denominator segment-sum.
// ---------------------------------------------------------------------------
template<int H>
__global__ void edge_exp(float* __restrict__ elog, const unsigned* __restrict__ smax,
                         float* __restrict__ den, const int* __restrict__ ei,
                         int E, int Etot)
{
    int t = blockIdx.x * blockDim.x + threadIdx.x;
    if (t >= Etot * H) return;
    int e = t / H, h = t - e * H;
    int d = (e < E) ? ei[E + e] : e - E;
    float m = dec_f(smax[d * H + h]);
    float ex = expf(elog[t] - m);
    elog[t] = ex;
    atomicAdd(&den[d * H + h], ex);
}

// ---------------------------------------------------------------------------
// Edge pass 3: agg[dst] += hw[src] * alpha.  One WARP per edge.
// ---------------------------------------------------------------------------
template<int F, int H>
__global__ void scatter_warp(const float* __restrict__ hw, const float* __restrict__ ex,
                             const float* __restrict__ den, const int* __restrict__ ei,
                             float* __restrict__ agg, int E, int Etot)
{
    int gw = (blockIdx.x * blockDim.x + threadIdx.x) >> 5;
    int lane = threadIdx.x & 31;
    if (gw >= Etot) return;
    int s, d;
    if (gw < E) { s = ei[gw]; d = ei[E + gw]; } else { s = d = gw - E; }
    float val = 0.f;
    if (lane < H)
        val = ex[(size_t)gw * H + lane] / (den[(size_t)d * H + lane] + 1e-16f);
    constexpr int C = F / H;
    #pragma unroll
    for (int i = 0; i < F / 128; i++) {
        int c = i * 128 + lane * 4;
        float a = __shfl_sync(0xffffffffu, val, c / C);
        float4 v = *(const float4*)(hw + (size_t)s * F + c);
        float* o = agg + (size_t)d * F + c;
        atomicAdd(o + 0, v.x * a);
        atomicAdd(o + 1, v.y * a);
        atomicAdd(o + 2, v.z * a);
        atomicAdd(o + 3, v.w * a);
    }
}

// ---------------------------------------------------------------------------
// bias + LayerNorm + ELU (+ optional residual, added AFTER elu).
// One block (256 threads) per node.
// ---------------------------------------------------------------------------
template<int F, bool RES>
__global__ __launch_bounds__(256)
void ln_elu(const float* __restrict__ agg, const float* __restrict__ bias,
            const float* __restrict__ gam, const float* __restrict__ bet,
            const float* __restrict__ res, float* __restrict__ out)
{
    constexpr int T = 256, P = F / T;
    int node = blockIdx.x, tid = threadIdx.x;
    __shared__ float sh[8];
    const float* row = agg + (size_t)node * F;
    float v[P];
    float s = 0.f;
    #pragma unroll
    for (int i = 0; i < P; i++) {
        int c = tid + i * T;
        v[i] = row[c] + bias[c];
        s += v[i];
    }
    s = blockSum(s, sh);
    float mu = s * (1.0f / F);
    float q = 0.f;
    #pragma unroll
    for (int i = 0; i < P; i++) { float dd = v[i] - mu; q += dd * dd; }
    q = blockSum(q, sh);
    float inv = rsqrtf(q * (1.0f / F) + 1e-5f);
    #pragma unroll
    for (int i = 0; i < P; i++) {
        int c = tid + i * T;
        float y = (v[i] - mu) * inv * gam[c] + bet[c];
        y = eluf(y);
        if (RES) y += res[(size_t)node * F + c];
        out[(size_t)node * F + c] = y;
    }
}

// ---------------------------------------------------------------------------
// Graph pooling
// ---------------------------------------------------------------------------
__global__ void pool_cnt(const int* __restrict__ batch, float* __restrict__ pcnt, int n)
{
    int t = blockIdx.x * blockDim.x + threadIdx.x;
    if (t < n) atomicAdd(&pcnt[batch[t]], 1.0f);
}

__global__ void pool_feat(const float* __restrict__ x3, const int* __restrict__ batch,
                          float* __restrict__ psum, unsigned* __restrict__ pmax, int n)
{
    int t = blockIdx.x * blockDim.x + threadIdx.x;
    if (t >= n * 256) return;
    int node = t >> 8, c = t & 255;
    int g = batch[node];
    float v = x3[t];
    atomicAdd(&psum[g * 256 + c], v);
    atomicMax(&pmax[g * 256 + c], enc_f(v));
}

// ---------------------------------------------------------------------------
// Classifier head: out[g] = relu(pooled @ W1 + b1) @ W2 + b2
// pooled[g] = [mean(256) | max(256) | sum(256)].  32 blocks x 128 threads.
// ---------------------------------------------------------------------------
__global__ __launch_bounds__(128)
void classifier(const float* __restrict__ psum, const unsigned* __restrict__ pmax,
                const float* __restrict__ pcnt,
                const float* __restrict__ w1, const float* __restrict__ b1,
                const float* __restrict__ w2, const float* __restrict__ b2,
                float* __restrict__ out)
{
    int g = blockIdx.x;
    int tid = threadIdx.x;
    __shared__ float p[768];
    __shared__ float r4[4];
    float cnt = fmaxf(pcnt[g], 1.0f);
    for (int i = tid; i < 768; i += 128) {
        float val;
        if (i < 256)      val = psum[g * 256 + i] / cnt;
        else if (i < 512) val = dec_f(pmax[g * 256 + (i - 256)]);
        else              val = psum[g * 256 + (i - 512)];
        p[i] = val;
    }
    __syncthreads();
    float acc = b1[tid];
    for (int k = 0; k < 768; k++) acc = fmaf(p[k], w1[k * 128 + tid], acc);
    float hv = fmaxf(acc, 0.0f) * w2[tid];
    hv = warpSum(hv);
    if ((tid & 31) == 0) r4[tid >> 5] = hv;
    __syncthreads();
    if (tid == 0) out[g] = r4[0] + r4[1] + r4[2] + r4[3] + b2[0];
}

// ---------------------------------------------------------------------------
// Launcher
// ---------------------------------------------------------------------------
extern "C" void kernel_launch(void* const* d_in, const int* in_sizes, int n_in,
                              void* d_out, int out_size)
{
    const float* x        = (const float*)d_in[0];
    const int*   ei       = (const int*)  d_in[1];
    const int*   batch    = (const int*)  d_in[2];
    const float* proj_w   = (const float*)d_in[3];
    const float* proj_b   = (const float*)d_in[4];
    const float* gat1_w   = (const float*)d_in[5];
    const float* att1_src = (const float*)d_in[6];
    const float* att1_dst = (const float*)d_in[7];
    const float* gat1_b   = (const float*)d_in[8];
    const float* ln1_g    = (const float*)d_in[9];
    const float* ln1_b    = (const float*)d_in[10];
    const float* gat2_w   = (const float*)d_in[11];
    const float* att2_src = (const float*)d_in[12];
    const float* att2_dst = (const float*)d_in[13];
    const float* gat2_b   = (const float*)d_in[14];
    const float* ln2_g    = (const float*)d_in[15];
    const float* ln2_b    = (const float*)d_in[16];
    const float* gat3_w   = (const float*)d_in[17];
    const float* att3_src = (const float*)d_in[18];
    const float* att3_dst = (const float*)d_in[19];
    const float* gat3_b   = (const float*)d_in[20];
    const float* ln3_g    = (const float*)d_in[21];
    const float* ln3_b    = (const float*)d_in[22];
    const float* cls1_w   = (const float*)d_in[23];
    const float* cls1_b   = (const float*)d_in[24];
    const float* cls2_w   = (const float*)d_in[25];
    const float* cls2_b   = (const float*)d_in[26];
    float* out = (float*)d_out;

    int n    = in_sizes[2];       // 20000
    int E    = in_sizes[1] / 2;   // 320000
    int Etot = E + n;

    float    *h_, *hw, *agg, *x1, *x2, *x3, *es_, *ed_, *den, *elog, *psum, *pcnt;
    unsigned *smax, *pmax;
    cudaGetSymbolAddress((void**)&h_,   g_h);
    cudaGetSymbolAddress((void**)&hw,   g_hw);
    cudaGetSymbolAddress((void**)&agg,  g_agg);
    cudaGetSymbolAddress((void**)&x1,   g_x1);
    cudaGetSymbolAddress((void**)&x2,   g_x2);
    cudaGetSymbolAddress((void**)&x3,   g_x3);
    cudaGetSymbolAddress((void**)&es_,  g_es);
    cudaGetSymbolAddress((void**)&ed_,  g_ed);
    cudaGetSymbolAddress((void**)&smax, g_smax);
    cudaGetSymbolAddress((void**)&den,  g_den);
    cudaGetSymbolAddress((void**)&elog, g_elog);
    cudaGetSymbolAddress((void**)&psum, g_psum);
    cudaGetSymbolAddress((void**)&pmax, g_pmax);
    cudaGetSymbolAddress((void**)&pcnt, g_pcnt);

    int mBlocks = (n + 127) / 128;
    int eThreads4 = (Etot * 4 + 255) / 256;
    int eThreads1 = (Etot + 255) / 256;
    int sBlocks   = (Etot * 32 + 255) / 256;   // warp-per-edge scatter

    // h = elu(x @ proj_w + proj_b)
    sgemm_f32x2<2><<<dim3(768 / 128, mBlocks), 256>>>(x, proj_w, proj_b, h_, n, 768, 768);

    // ---------------- GAT layer 1 (H=4, C=256, F=1024) ----------------
    sgemm_f32x2<0><<<dim3(1024 / 128, mBlocks), 256>>>(h_, gat1_w, nullptr, hw, n, 1024, 768);
    attn_scores<<<(n * 4 + 7) / 8, 256>>>(hw, att1_src, att1_dst, es_, ed_, n, 4, 256);
    cudaMemsetAsync(smax, 0, (size_t)n * 4 * sizeof(unsigned), 0);
    cudaMemsetAsync(den,  0, (size_t)n * 4 * sizeof(float), 0);
    cudaMemsetAsync(agg,  0, (size_t)n * 1024 * sizeof(float), 0);
    edge_logits<4><<<eThreads4, 256>>>(es_, ed_, ei, elog, smax, E, Etot);
    edge_exp<4><<<eThreads4, 256>>>(elog, smax, den, ei, E, Etot);
    scatter_warp<1024, 4><<<sBlocks, 256>>>(hw, elog, den, ei, agg, E, Etot);
    ln_elu<1024, false><<<n, 256>>>(agg, gat1_b, ln1_g, ln1_b, nullptr, x1);

    // ---------------- GAT layer 2 (H=4, C=256, F=1024, residual) -------
    sgemm_f32x2<0><<<dim3(1024 / 128, mBlocks), 256>>>(x1, gat2_w, nullptr, hw, n, 1024, 1024);
    attn_scores<<<(n * 4 + 7) / 8, 256>>>(hw, att2_src, att2_dst, es_, ed_, n, 4, 256);
    cudaMemsetAsync(smax, 0, (size_t)n * 4 * sizeof(unsigned), 0);
    cudaMemsetAsync(den,  0, (size_t)n * 4 * sizeof(float), 0);
    cudaMemsetAsync(agg,  0, (size_t)n * 1024 * sizeof(float), 0);
    edge_logits<4><<<eThreads4, 256>>>(es_, ed_, ei, elog, smax, E, Etot);
    edge_exp<4><<<eThreads4, 256>>>(elog, smax, den, ei, E, Etot);
    scatter_warp<1024, 4><<<sBlocks, 256>>>(hw, elog, den, ei, agg, E, Etot);
    ln_elu<1024, true><<<n, 256>>>(agg, gat2_b, ln2_g, ln2_b, x1, x2);

    // ---------------- GAT layer 3 (H=1, C=256, F=256) -------------------
    sgemm_f32x2<0><<<dim3(256 / 128, mBlocks), 256>>>(x2, gat3_w, nullptr, hw, n, 256, 1024);
    attn_scores<<<(n + 7) / 8, 256>>>(hw, att3_src, att3_dst, es_, ed_, n, 1, 256);
    cudaMemsetAsync(smax, 0, (size_t)n * sizeof(unsigned), 0);
    cudaMemsetAsync(den,  0, (size_t)n * sizeof(float), 0);
    cudaMemsetAsync(agg,  0, (size_t)n * 256 * sizeof(float), 0);
    edge_logits<1><<<eThreads1, 256>>>(es_, ed_, ei, elog, smax, E, Etot);
    edge_exp<1><<<eThreads1, 256>>>(elog, smax, den, ei, E, Etot);
    scatter_warp<256, 1><<<sBlocks, 256>>>(hw, elog, den, ei, agg, E, Etot);
    ln_elu<256, false><<<n, 256>>>(agg, gat3_b, ln3_g, ln3_b, nullptr, x3);

    // ---------------- Pooling + classifier ------------------------------
    cudaMemsetAsync(psum, 0, (size_t)GMAX * 256 * sizeof(float), 0);
    cudaMemsetAsync(pmax, 0, (size_t)GMAX * 256 * sizeof(unsigned), 0);
    cudaMemsetAsync(pcnt, 0, (size_t)GMAX * sizeof(float), 0);
    pool_cnt<<<(n + 255) / 256, 256>>>(batch, pcnt, n);
    pool_feat<<<(n * 256 + 255) / 256, 256>>>(x3, batch, psum, pmax, n);
    classifier<<<GMAX, 128>>>(psum, pmax, pcnt, cls1_w, cls1_b, cls2_w, cls2_b, out);
}

// round 3
// speedup vs baseline: 1.6213x; 1.4576x over previous
#include <cuda_runtime.h>
#include <cuda_bf16.h>
#include <math.h>

// ---------------------------------------------------------------------------
// Problem constants (fixed by the dataset)
// ---------------------------------------------------------------------------
#define NMAX   20000
#define EMAX   320000
#define ETOTMX (EMAX + NMAX)
#define GMAX   32

// ---------------------------------------------------------------------------
// Scratch (device globals; no allocations allowed anywhere)
// ---------------------------------------------------------------------------
__device__ float    g_h    [NMAX * 768];    // proj output
__device__ float    g_hw   [NMAX * 1024];   // GAT linear output (per layer, reused)
__device__ float    g_x1   [NMAX * 1024];
__device__ float    g_x2   [NMAX * 1024];
__device__ float    g_es   [NMAX * 4];
__device__ float    g_ed   [NMAX * 4];
__device__ int      g_deg  [NMAX + 1];
__device__ int      g_rowp [NMAX + 1];
__device__ int      g_wo   [NMAX];
__device__ int      g_csrs [ETOTMX];        // src node per CSR slot (by dst)
__device__ float    g_psum [GMAX * 256];
__device__ unsigned g_pmax [GMAX * 256];
__device__ float    g_pcnt [GMAX];

// ---------------------------------------------------------------------------
// Helpers
// ---------------------------------------------------------------------------
__device__ __forceinline__ unsigned enc_f(float f) {
    unsigned u = __float_as_uint(f);
    return (u & 0x80000000u) ? ~u : (u | 0x80000000u);
}
__device__ __forceinline__ float dec_f(unsigned k) {
    unsigned u = (k & 0x80000000u) ? (k & 0x7fffffffu) : ~k;
    return __uint_as_float(u);
}
__device__ __forceinline__ float warpSum(float v) {
    #pragma unroll
    for (int o = 16; o > 0; o >>= 1) v += __shfl_xor_sync(0xffffffffu, v, o);
    return v;
}
__device__ __forceinline__ float blockSum(float v, float* sh) {
    int lane = threadIdx.x & 31, w = threadIdx.x >> 5;
    int nw = blockDim.x >> 5;
    v = warpSum(v);
    __syncthreads();
    if (lane == 0) sh[w] = v;
    __syncthreads();
    float r = (threadIdx.x < nw) ? sh[threadIdx.x] : 0.0f;
    if (w == 0) {
        r = warpSum(r);
        if (lane == 0) sh[0] = r;
    }
    __syncthreads();
    return sh[0];
}
__device__ __forceinline__ float eluf(float x) { return x > 0.0f ? x : expm1f(x); }

// Packed f32x2 primitives (sm_103a FFMA2 path — ptxas won't auto-fuse)
__device__ __forceinline__ unsigned long long dupf(float a) {
    unsigned long long r;
    asm("mov.b64 %0, {%1, %1};" : "=l"(r) : "f"(a));
    return r;
}
__device__ __forceinline__ void ffma2(unsigned long long& acc,
                                      unsigned long long a, unsigned long long b) {
    asm("fma.rn.f32x2 %0, %1, %2, %0;" : "+l"(acc) : "l"(a), "l"(b));
}
__device__ __forceinline__ float2 unpk(unsigned long long v) {
    float lo, hi;
    asm("mov.b64 {%0, %1}, %2;" : "=f"(lo), "=f"(hi) : "l"(v));
    return make_float2(lo, hi);
}

// ---------------------------------------------------------------------------
// GEMM: C[M,N] = A[M,K] @ B[K,N], row-major. FFMA2-packed fp32.
// 128x128 tile, BK=16, 256 threads, 8x8 per thread (as 8x4 packed pairs).
// ---------------------------------------------------------------------------
template<int EPI>
__global__ __launch_bounds__(256, 2)
void sgemm_f32x2(const float* __restrict__ A, const float* __restrict__ B,
                 const float* __restrict__ bias, float* __restrict__ C,
                 int M, int N, int K)
{
    __shared__ __align__(16) float As[2][16][128];
    __shared__ __align__(16) float Bs[2][16][128];

    const int tid = threadIdx.x;
    const int tx = tid & 15, ty = tid >> 4;
    const int row0 = blockIdx.y * 128, col0 = blockIdx.x * 128;

    unsigned long long acc[8][4];
    #pragma unroll
    for (int i = 0; i < 8; i++)
        #pragma unroll
        for (int j = 0; j < 4; j++) acc[i][j] = 0ull;

    const int arow = tid >> 1, akoff = (tid & 1) * 8;
    const bool avalid = (row0 + arow) < M;
    const float* Abase = A + (size_t)(row0 + arow) * K + akoff;
    const float* Bbase0 = B + (size_t)(tid >> 5) * N + col0 + (tid & 31) * 4;
    const float* Bbase1 = B + (size_t)((tid + 256) >> 5) * N + col0 + (tid & 31) * 4;
    const int nk = K >> 4;

    float4 pa0, pa1, pb0, pb1;
    pa0 = avalid ? *(const float4*)(Abase + 0) : make_float4(0.f, 0.f, 0.f, 0.f);
    pa1 = avalid ? *(const float4*)(Abase + 4) : make_float4(0.f, 0.f, 0.f, 0.f);
    pb0 = *(const float4*)(Bbase0);
    pb1 = *(const float4*)(Bbase1);

    int buf = 0;
    As[buf][akoff + 0][arow] = pa0.x; As[buf][akoff + 1][arow] = pa0.y;
    As[buf][akoff + 2][arow] = pa0.z; As[buf][akoff + 3][arow] = pa0.w;
    As[buf][akoff + 4][arow] = pa1.x; As[buf][akoff + 5][arow] = pa1.y;
    As[buf][akoff + 6][arow] = pa1.z; As[buf][akoff + 7][arow] = pa1.w;
    *(float4*)&Bs[buf][tid >> 5][(tid & 31) * 4] = pb0;
    *(float4*)&Bs[buf][(tid + 256) >> 5][(tid & 31) * 4] = pb1;
    __syncthreads();

    for (int ch = 0; ch < nk; ch++) {
        const bool has_next = (ch + 1) < nk;
        if (has_next) {
            const float* Ap = Abase + (size_t)(ch + 1) * 16;
            pa0 = avalid ? *(const float4*)(Ap + 0) : make_float4(0.f, 0.f, 0.f, 0.f);
            pa1 = avalid ? *(const float4*)(Ap + 4) : make_float4(0.f, 0.f, 0.f, 0.f);
            pb0 = *(const float4*)(Bbase0 + (size_t)(ch + 1) * 16 * N);
            pb1 = *(const float4*)(Bbase1 + (size_t)(ch + 1) * 16 * N);
        }
        #pragma unroll
        for (int k = 0; k < 16; k++) {
            float4 a0 = *(const float4*)&As[buf][k][ty * 8];
            float4 a1 = *(const float4*)&As[buf][k][ty * 8 + 4];
            ulonglong2 b01 = *(const ulonglong2*)&Bs[buf][k][tx * 8];
            ulonglong2 b23 = *(const ulonglong2*)&Bs[buf][k][tx * 8 + 4];
            float av[8] = {a0.x, a0.y, a0.z, a0.w, a1.x, a1.y, a1.z, a1.w};
            #pragma unroll
            for (int i = 0; i < 8; i++) {
                unsigned long long ad = dupf(av[i]);
                ffma2(acc[i][0], ad, b01.x);
                ffma2(acc[i][1], ad, b01.y);
                ffma2(acc[i][2], ad, b23.x);
                ffma2(acc[i][3], ad, b23.y);
            }
        }
        if (has_next) {
            int nb = buf ^ 1;
            As[nb][akoff + 0][arow] = pa0.x; As[nb][akoff + 1][arow] = pa0.y;
            As[nb][akoff + 2][arow] = pa0.z; As[nb][akoff + 3][arow] = pa0.w;
            As[nb][akoff + 4][arow] = pa1.x; As[nb][akoff + 5][arow] = pa1.y;
            As[nb][akoff + 6][arow] = pa1.z; As[nb][akoff + 7][arow] = pa1.w;
            *(float4*)&Bs[nb][tid >> 5][(tid & 31) * 4] = pb0;
            *(float4*)&Bs[nb][(tid + 256) >> 5][(tid & 31) * 4] = pb1;
        }
        __syncthreads();
        buf ^= 1;
    }

    #pragma unroll
    for (int i = 0; i < 8; i++) {
        int r = row0 + ty * 8 + i;
        if (r >= M) break;
        float o[8];
        #pragma unroll
        for (int j = 0; j < 4; j++) {
            float2 p = unpk(acc[i][j]);
            o[2 * j] = p.x; o[2 * j + 1] = p.y;
        }
        int c = col0 + tx * 8;
        #pragma unroll
        for (int j = 0; j < 8; j++) {
            if (EPI >= 1) o[j] += bias[c + j];
            if (EPI == 2) o[j] = eluf(o[j]);
        }
        float* Cp = C + (size_t)r * N + c;
        *(float4*)(Cp)     = make_float4(o[0], o[1], o[2], o[3]);
        *(float4*)(Cp + 4) = make_float4(o[4], o[5], o[6], o[7]);
    }
}

// ---------------------------------------------------------------------------
// CSR build (by destination). Deterministic degrees; slot order via atomics.
// ---------------------------------------------------------------------------
__global__ void deg_count(const int* __restrict__ ei, int* __restrict__ deg,
                          int E, int Etot)
{
    int e = blockIdx.x * blockDim.x + threadIdx.x;
    if (e >= Etot) return;
    int d = (e < E) ? ei[E + e] : e - E;
    atomicAdd(&deg[d], 1);
}

__global__ __launch_bounds__(256)
void scan_rowptr(const int* __restrict__ deg, int* __restrict__ rowp, int n)
{
    __shared__ int part[256];
    int tid = threadIdx.x;
    int chunk = (n + 255) / 256;
    int lo = tid * chunk;
    int hi = min(lo + chunk, n);
    int s = 0;
    for (int i = lo; i < hi; i++) s += deg[i];
    part[tid] = s;
    __syncthreads();
    for (int off = 1; off < 256; off <<= 1) {
        int v = (tid >= off) ? part[tid - off] : 0;
        __syncthreads();
        part[tid] += v;
        __syncthreads();
    }
    int base = (tid == 0) ? 0 : part[tid - 1];
    for (int i = lo; i < hi; i++) { rowp[i] = base; base += deg[i]; }
    if (tid == 255) rowp[n] = part[255];
}

__global__ void csr_place(const int* __restrict__ ei, const int* __restrict__ rowp,
                          int* __restrict__ wo, int* __restrict__ csrs,
                          int E, int Etot)
{
    int e = blockIdx.x * blockDim.x + threadIdx.x;
    if (e >= Etot) return;
    int s, d;
    if (e < E) { s = ei[e]; d = ei[E + e]; } else { s = d = e - E; }
    int pos = atomicAdd(&wo[d], 1);
    csrs[rowp[d] + pos] = s;
}

// ---------------------------------------------------------------------------
// Attention scores: es[n,h] = sum_c hw[n,h,c]*a_src[h,c]; ed likewise.
// ---------------------------------------------------------------------------
__global__ void attn_scores(const float* __restrict__ hw,
                            const float* __restrict__ a_src,
                            const float* __restrict__ a_dst,
                            float* __restrict__ es, float* __restrict__ ed,
                            int n, int H, int C)
{
    int gw = (blockIdx.x * blockDim.x + threadIdx.x) >> 5;
    int lane = threadIdx.x & 31;
    int node = gw / H, h = gw % H;
    if (node >= n) return;
    const float* row = hw + (size_t)node * H * C + h * C;
    const float* as = a_src + h * C;
    const float* ad = a_dst + h * C;
    float ss = 0.f, sd = 0.f;
    for (int c = lane; c < C; c += 32) {
        float v = row[c];
        ss = fmaf(v, as[c], ss);
        sd = fmaf(v, ad[c], sd);
    }
    ss = warpSum(ss);
    sd = warpSum(sd);
    if (lane == 0) { es[node * H + h] = ss; ed[node * H + h] = sd; }
}

// ---------------------------------------------------------------------------
// Fused GAT aggregation: per dst node, 3 register passes over incoming edges
// (max -> den -> weighted gather), then bias+LN+ELU(+residual) and either
// store the row or (layer 3) scatter straight into the pooling accumulators.
// One block of F/4 threads per node; thread handles 4 consecutive features.
// ---------------------------------------------------------------------------
template<int F, int H, bool RES, bool POOL>
__global__ __launch_bounds__(F / 4)
void gather_ln(const float* __restrict__ hw,
               const float* __restrict__ es, const float* __restrict__ ed,
               const int* __restrict__ rowp, const int* __restrict__ csrs,
               const float* __restrict__ bias,
               const float* __restrict__ gam, const float* __restrict__ bet,
               const float* __restrict__ res, float* __restrict__ out,
               const int* __restrict__ batch,
               float* __restrict__ psum, unsigned* __restrict__ pmax)
{
    constexpr int T = F / 4;
    constexpr int C = F / H;
    __shared__ float sh[T / 32 > 1 ? T / 32 : 1];

    const int d = blockIdx.x;
    const int tid = threadIdx.x;
    const int c = tid * 4;
    const int h = c / C;
    const int start = rowp[d];
    const int end = rowp[d + 1];
    const float edh = ed[d * H + h];

    // pass A: segment max of leaky_relu(es[s]+ed[d]) for this head
    float mx = -1e30f;
    for (int i = start; i < end; i++) {
        int s = csrs[i];
        float l = es[s * H + h] + edh;
        l = l > 0.0f ? l : 0.2f * l;
        mx = fmaxf(mx, l);
    }
    // pass B: denominator
    float den = 0.0f;
    for (int i = start; i < end; i++) {
        int s = csrs[i];
        float l = es[s * H + h] + edh;
        l = l > 0.0f ? l : 0.2f * l;
        den += expf(l - mx);
    }
    const float dinv = 1.0f / (den + 1e-16f);
    // pass C: weighted gather of hw rows
    float4 acc = make_float4(0.f, 0.f, 0.f, 0.f);
    for (int i = start; i < end; i++) {
        int s = csrs[i];
        float l = es[s * H + h] + edh;
        l = l > 0.0f ? l : 0.2f * l;
        float a = expf(l - mx) * dinv;
        float4 v = *(const float4*)(hw + (size_t)s * F + c);
        acc.x = fmaf(v.x, a, acc.x);
        acc.y = fmaf(v.y, a, acc.y);
        acc.z = fmaf(v.z, a, acc.z);
        acc.w = fmaf(v.w, a, acc.w);
    }

    // bias + LayerNorm + ELU (+ residual) fully fused
    float4 b4 = *(const float4*)(bias + c);
    float v0 = acc.x + b4.x, v1 = acc.y + b4.y, v2 = acc.z + b4.z, v3 = acc.w + b4.w;
    float ssum = blockSum(v0 + v1 + v2 + v3, sh);
    float mu = ssum * (1.0f / F);
    float d0 = v0 - mu, d1 = v1 - mu, d2 = v2 - mu, d3 = v3 - mu;
    float q = blockSum(d0 * d0 + d1 * d1 + d2 * d2 + d3 * d3, sh);
    float inv = rsqrtf(q * (1.0f / F) + 1e-5f);
    float4 g4 = *(const float4*)(gam + c);
    float4 be4 = *(const float4*)(bet + c);
    float y0 = eluf(d0 * inv * g4.x + be4.x);
    float y1 = eluf(d1 * inv * g4.y + be4.y);
    float y2 = eluf(d2 * inv * g4.z + be4.z);
    float y3 = eluf(d3 * inv * g4.w + be4.w);
    if (RES) {
        const float* rp = res + (size_t)d * F + c;
        y0 += rp[0]; y1 += rp[1]; y2 += rp[2]; y3 += rp[3];
    }
    if (POOL) {
        int g = batch[d];
        float* ps = psum + g * 256 + c;
        unsigned* pm = pmax + g * 256 + c;
        atomicAdd(ps + 0, y0); atomicMax(pm + 0, enc_f(y0));
        atomicAdd(ps + 1, y1); atomicMax(pm + 1, enc_f(y1));
        atomicAdd(ps + 2, y2); atomicMax(pm + 2, enc_f(y2));
        atomicAdd(ps + 3, y3); atomicMax(pm + 3, enc_f(y3));
    } else {
        *(float4*)(out + (size_t)d * F + c) = make_float4(y0, y1, y2, y3);
    }
}

// ---------------------------------------------------------------------------
// Graph pooling count + classifier head
// ---------------------------------------------------------------------------
__global__ void pool_cnt(const int* __restrict__ batch, float* __restrict__ pcnt, int n)
{
    int t = blockIdx.x * blockDim.x + threadIdx.x;
    if (t < n) atomicAdd(&pcnt[batch[t]], 1.0f);
}

__global__ __launch_bounds__(128)
void classifier(const float* __restrict__ psum, const unsigned* __restrict__ pmax,
                const float* __restrict__ pcnt,
                const float* __restrict__ w1, const float* __restrict__ b1,
                const float* __restrict__ w2, const float* __restrict__ b2,
                float* __restrict__ out)
{
    int g = blockIdx.x;
    int tid = threadIdx.x;
    __shared__ float p[768];
    __shared__ float r4[4];
    float cnt = fmaxf(pcnt[g], 1.0f);
    for (int i = tid; i < 768; i += 128) {
        float val;
        if (i < 256)      val = psum[g * 256 + i] / cnt;
        else if (i < 512) val = dec_f(pmax[g * 256 + (i - 256)]);
        else              val = psum[g * 256 + (i - 512)];
        p[i] = val;
    }
    __syncthreads();
    float acc = b1[tid];
    for (int k = 0; k < 768; k++) acc = fmaf(p[k], w1[k * 128 + tid], acc);
    float hv = fmaxf(acc, 0.0f) * w2[tid];
    hv = warpSum(hv);
    if ((tid & 31) == 0) r4[tid >> 5] = hv;
    __syncthreads();
    if (tid == 0) out[g] = r4[0] + r4[1] + r4[2] + r4[3] + b2[0];
}

// ---------------------------------------------------------------------------
// Launcher
// ---------------------------------------------------------------------------
extern "C" void kernel_launch(void* const* d_in, const int* in_sizes, int n_in,
                              void* d_out, int out_size)
{
    const float* x        = (const float*)d_in[0];
    const int*   ei       = (const int*)  d_in[1];
    const int*   batch    = (const int*)  d_in[2];
    const float* proj_w   = (const float*)d_in[3];
    const float* proj_b   = (const float*)d_in[4];
    const float* gat1_w   = (const float*)d_in[5];
    const float* att1_src = (const float*)d_in[6];
    const float* att1_dst = (const float*)d_in[7];
    const float* gat1_b   = (const float*)d_in[8];
    const float* ln1_g    = (const float*)d_in[9];
    const float* ln1_b    = (const float*)d_in[10];
    const float* gat2_w   = (const float*)d_in[11];
    const float* att2_src = (const float*)d_in[12];
    const float* att2_dst = (const float*)d_in[13];
    const float* gat2_b   = (const float*)d_in[14];
    const float* ln2_g    = (const float*)d_in[15];
    const float* ln2_b    = (const float*)d_in[16];
    const float* gat3_w   = (const float*)d_in[17];
    const float* att3_src = (const float*)d_in[18];
    const float* att3_dst = (const float*)d_in[19];
    const float* gat3_b   = (const float*)d_in[20];
    const float* ln3_g    = (const float*)d_in[21];
    const float* ln3_b    = (const float*)d_in[22];
    const float* cls1_w   = (const float*)d_in[23];
    const float* cls1_b   = (const float*)d_in[24];
    const float* cls2_w   = (const float*)d_in[25];
    const float* cls2_b   = (const float*)d_in[26];
    float* out = (float*)d_out;

    int n    = in_sizes[2];       // 20000
    int E    = in_sizes[1] / 2;   // 320000
    int Etot = E + n;

    float *h_, *hw, *x1, *x2, *es_, *ed_, *psum, *pcnt;
    int *deg, *rowp, *wo, *csrs;
    unsigned *pmax;
    cudaGetSymbolAddress((void**)&h_,   g_h);
    cudaGetSymbolAddress((void**)&hw,   g_hw);
    cudaGetSymbolAddress((void**)&x1,   g_x1);
    cudaGetSymbolAddress((void**)&x2,   g_x2);
    cudaGetSymbolAddress((void**)&es_,  g_es);
    cudaGetSymbolAddress((void**)&ed_,  g_ed);
    cudaGetSymbolAddress((void**)&deg,  g_deg);
    cudaGetSymbolAddress((void**)&rowp, g_rowp);
    cudaGetSymbolAddress((void**)&wo,   g_wo);
    cudaGetSymbolAddress((void**)&csrs, g_csrs);
    cudaGetSymbolAddress((void**)&psum, g_psum);
    cudaGetSymbolAddress((void**)&pmax, g_pmax);
    cudaGetSymbolAddress((void**)&pcnt, g_pcnt);

    int mBlocks = (n + 127) / 128;
    int eBlocks = (Etot + 255) / 256;

    // ---- CSR build (independent of features; runs up front) ----
    cudaMemsetAsync(deg, 0, (size_t)(n + 1) * sizeof(int), 0);
    cudaMemsetAsync(wo,  0, (size_t)n * sizeof(int), 0);
    deg_count<<<eBlocks, 256>>>(ei, deg, E, Etot);
    scan_rowptr<<<1, 256>>>(deg, rowp, n);
    csr_place<<<eBlocks, 256>>>(ei, rowp, wo, csrs, E, Etot);

    // ---- pooling accumulator init (used by layer 3) ----
    cudaMemsetAsync(psum, 0, (size_t)GMAX * 256 * sizeof(float), 0);
    cudaMemsetAsync(pmax, 0, (size_t)GMAX * 256 * sizeof(unsigned), 0);
    cudaMemsetAsync(pcnt, 0, (size_t)GMAX * sizeof(float), 0);
    pool_cnt<<<(n + 255) / 256, 256>>>(batch, pcnt, n);

    // h = elu(x @ proj_w + proj_b)
    sgemm_f32x2<2><<<dim3(768 / 128, mBlocks), 256>>>(x, proj_w, proj_b, h_, n, 768, 768);

    // ---------------- GAT layer 1 (H=4, C=256, F=1024) ----------------
    sgemm_f32x2<0><<<dim3(1024 / 128, mBlocks), 256>>>(h_, gat1_w, nullptr, hw, n, 1024, 768);
    attn_scores<<<(n * 4 + 7) / 8, 256>>>(hw, att1_src, att1_dst, es_, ed_, n, 4, 256);
    gather_ln<1024, 4, false, false><<<n, 256>>>(hw, es_, ed_, rowp, csrs,
        gat1_b, ln1_g, ln1_b, nullptr, x1, nullptr, nullptr, nullptr);

    // ---------------- GAT layer 2 (H=4, C=256, F=1024, residual) -------
    sgemm_f32x2<0><<<dim3(1024 / 128, mBlocks), 256>>>(x1, gat2_w, nullptr, hw, n, 1024, 1024);
    attn_scores<<<(n * 4 + 7) / 8, 256>>>(hw, att2_src, att2_dst, es_, ed_, n, 4, 256);
    gather_ln<1024, 4, true, false><<<n, 256>>>(hw, es_, ed_, rowp, csrs,
        gat2_b, ln2_g, ln2_b, x1, x2, nullptr, nullptr, nullptr);

    // ---------------- GAT layer 3 (H=1, C=256, F=256) + fused pooling ---
    sgemm_f32x2<0><<<dim3(256 / 128, mBlocks), 256>>>(x2, gat3_w, nullptr, hw, n, 256, 1024);
    attn_scores<<<(n + 7) / 8, 256>>>(hw, att3_src, att3_dst, es_, ed_, n, 1, 256);
    gather_ln<256, 1, false, true><<<n, 64>>>(hw, es_, ed_, rowp, csrs,
        gat3_b, ln3_g, ln3_b, nullptr, nullptr, batch, psum, pmax);

    // ---------------- Classifier ----------------------------------------
    classifier<<<GMAX, 128>>>(psum, pmax, pcnt, cls1_w, cls1_b, cls2_w, cls2_b, out);
}

// round 8
// speedup vs baseline: 2.6224x; 1.6174x over previous
#include <cuda_runtime.h>
#include <cuda_bf16.h>
#include <math.h>
#include <stdint.h>

// ---------------------------------------------------------------------------
// Problem constants
// ---------------------------------------------------------------------------
#define NMAX   20000
#define EMAX   320000
#define ETOTMX (EMAX + NMAX)
#define GMAX   32

// ---------------------------------------------------------------------------
// Scratch (device globals; no allocations allowed anywhere)
// ---------------------------------------------------------------------------
__device__ float         g_h   [NMAX * 768];
__device__ float         g_hw  [NMAX * 1024];
__device__ float         g_x1  [NMAX * 1024];
__device__ float         g_x2  [NMAX * 1024];
__device__ __nv_bfloat16 g_ah  [NMAX * 1024];
__device__ __nv_bfloat16 g_al  [NMAX * 1024];
__device__ __nv_bfloat16 g_bh  [1024 * 1024];
__device__ __nv_bfloat16 g_bl  [1024 * 1024];
__device__ float         g_es  [NMAX * 4];
__device__ float         g_ed  [NMAX * 4];
__device__ int           g_deg [NMAX + 1];
__device__ int           g_rowp[NMAX + 1];
__device__ int           g_wo  [NMAX];
__device__ int           g_csrs[ETOTMX];
__device__ float         g_psum[GMAX * 256];
__device__ unsigned      g_pmax[GMAX * 256];
__device__ float         g_pcnt[GMAX];

// ---------------------------------------------------------------------------
// Helpers
// ---------------------------------------------------------------------------
__device__ __forceinline__ unsigned enc_f(float f) {
    unsigned u = __float_as_uint(f);
    return (u & 0x80000000u) ? ~u : (u | 0x80000000u);
}
__device__ __forceinline__ float dec_f(unsigned k) {
    unsigned u = (k & 0x80000000u) ? (k & 0x7fffffffu) : ~k;
    return __uint_as_float(u);
}
__device__ __forceinline__ float warpSum(float v) {
    #pragma unroll
    for (int o = 16; o > 0; o >>= 1) v += __shfl_xor_sync(0xffffffffu, v, o);
    return v;
}
__device__ __forceinline__ float blockSum(float v, float* sh) {
    int lane = threadIdx.x & 31, w = threadIdx.x >> 5;
    int nw = blockDim.x >> 5;
    v = warpSum(v);
    __syncthreads();
    if (lane == 0) sh[w] = v;
    __syncthreads();
    float r = (threadIdx.x < nw) ? sh[threadIdx.x] : 0.0f;
    if (w == 0) {
        r = warpSum(r);
        if (lane == 0) sh[0] = r;
    }
    __syncthreads();
    return sh[0];
}
__device__ __forceinline__ float eluf(float x) { return x > 0.0f ? x : expm1f(x); }

__device__ __forceinline__ uint32_t s2u(const void* p) {
    uint32_t a;
    asm("{ .reg .u64 t; cvta.to.shared.u64 t, %1; cvt.u32.u64 %0, t; }"
        : "=r"(a) : "l"(p));
    return a;
}
// ldmatrix x4 (sm_75+, valid on plain sm_103)
__device__ __forceinline__ void ldm4(uint32_t* r, uint32_t addr) {
    asm volatile("ldmatrix.sync.aligned.m8n8.x4.shared.b16 {%0,%1,%2,%3}, [%4];"
                 : "=r"(r[0]), "=r"(r[1]), "=r"(r[2]), "=r"(r[3]) : "r"(addr));
}
// mma.sync m16n8k16 bf16 -> f32 (sm_80+, valid on plain sm_103)
__device__ __forceinline__ void mma16816(float* c, const uint32_t* a, const uint32_t* b) {
    asm volatile(
        "mma.sync.aligned.m16n8k16.row.col.f32.bf16.bf16.f32 "
        "{%0,%1,%2,%3}, {%4,%5,%6,%7}, {%8,%9}, {%0,%1,%2,%3};"
        : "+f"(c[0]), "+f"(c[1]), "+f"(c[2]), "+f"(c[3])
        : "r"(a[0]), "r"(a[1]), "r"(a[2]), "r"(a[3]), "r"(b[0]), "r"(b[1]));
}

// ---------------------------------------------------------------------------
// Split A (fp32 -> bf16 hi + bf16 lo residual)
// ---------------------------------------------------------------------------
__global__ void split_a(const float* __restrict__ in,
                        __nv_bfloat16* __restrict__ hi,
                        __nv_bfloat16* __restrict__ lo, int total)
{
    int i = (blockIdx.x * blockDim.x + threadIdx.x) * 4;
    if (i >= total) return;
    float4 v = *(const float4*)(in + i);
    __nv_bfloat16 h0 = __float2bfloat16(v.x), h1 = __float2bfloat16(v.y);
    __nv_bfloat16 h2 = __float2bfloat16(v.z), h3 = __float2bfloat16(v.w);
    __nv_bfloat16 l0 = __float2bfloat16(v.x - __bfloat162float(h0));
    __nv_bfloat16 l1 = __float2bfloat16(v.y - __bfloat162float(h1));
    __nv_bfloat16 l2 = __float2bfloat16(v.z - __bfloat162float(h2));
    __nv_bfloat16 l3 = __float2bfloat16(v.w - __bfloat162float(h3));
    *(__nv_bfloat162*)(hi + i)     = __nv_bfloat162(h0, h1);
    *(__nv_bfloat162*)(hi + i + 2) = __nv_bfloat162(h2, h3);
    *(__nv_bfloat162*)(lo + i)     = __nv_bfloat162(l0, l1);
    *(__nv_bfloat162*)(lo + i + 2) = __nv_bfloat162(l2, l3);
}

// ---------------------------------------------------------------------------
// Transpose + split W: W[K,N] fp32 -> Bh,Bl [N,K] bf16
// ---------------------------------------------------------------------------
__global__ __launch_bounds__(256)
void tsplit_w(const float* __restrict__ W,
              __nv_bfloat16* __restrict__ bh, __nv_bfloat16* __restrict__ bl,
              int K, int N)
{
    __shared__ float t[32][33];
    int n0 = blockIdx.x * 32, k0 = blockIdx.y * 32;
    int tx = threadIdx.x & 31, ty = threadIdx.x >> 5;
    #pragma unroll
    for (int r = ty; r < 32; r += 8)
        t[r][tx] = W[(size_t)(k0 + r) * N + n0 + tx];
    __syncthreads();
    #pragma unroll
    for (int r = ty; r < 32; r += 8) {
        float v = t[tx][r];
        __nv_bfloat16 h = __float2bfloat16(v);
        bh[(size_t)(n0 + r) * K + k0 + tx] = h;
        bl[(size_t)(n0 + r) * K + k0 + tx] = __float2bfloat16(v - __bfloat162float(h));
    }
}

// ---------------------------------------------------------------------------
// HMMA GEMM via ldmatrix + mma.sync, bf16 3-split (AhBh + AhBl + AlBh).
// C[M,N] = A[M,K] @ W[K,N].  A hi/lo: [M,K] bf16.  B hi/lo: [N,K] bf16.
// Block 128x128, BK=32, 8 warps (4m x 2n), warp tile 32x64.
// smem rows padded to 40 bf16 (80B) -> conflict-free ldmatrix.
// EPI: 0 none, 1 +bias, 2 +bias+ELU.
// ---------------------------------------------------------------------------
template<int EPI>
__global__ __launch_bounds__(256)
void hmma_gemm(const __nv_bfloat16* __restrict__ Ah, const __nv_bfloat16* __restrict__ Al,
               const __nv_bfloat16* __restrict__ Bh, const __nv_bfloat16* __restrict__ Bl,
               const float* __restrict__ bias, float* __restrict__ C,
               int M, int N, int K)
{
    __shared__ __nv_bfloat16 sAh[128][40];
    __shared__ __nv_bfloat16 sAl[128][40];
    __shared__ __nv_bfloat16 sBh[128][40];
    __shared__ __nv_bfloat16 sBl[128][40];

    const int tid = threadIdx.x;
    const int lane = tid & 31, wid = tid >> 5;
    const int wm = wid & 3, wn = wid >> 2;            // 4 x 2 warp grid
    const int row0 = blockIdx.y * 128, col0 = blockIdx.x * 128;

    float c[2][8][4];
    #pragma unroll
    for (int i = 0; i < 2; i++)
        #pragma unroll
        for (int j = 0; j < 8; j++)
            #pragma unroll
            for (int q = 0; q < 4; q++) c[i][j][q] = 0.0f;

    // gmem load mapping: 512 uint4 per 128x32 tile; thread does u = tid, tid+256
    int lrow[2], lseg[2];
    #pragma unroll
    for (int i = 0; i < 2; i++) { int u = i * 256 + tid; lrow[i] = u >> 2; lseg[i] = u & 3; }

    const int nkc = K >> 5;
    uint4 pah[2], pal[2], pbh[2], pbl[2];
    const uint4 zz = make_uint4(0u, 0u, 0u, 0u);

    auto LOADC = [&](int kc) {
        #pragma unroll
        for (int i = 0; i < 2; i++) {
            int ar = row0 + lrow[i];
            bool ok = ar < M;
            size_t ka = (size_t)ar * K + kc * 32 + lseg[i] * 8;
            pah[i] = ok ? *(const uint4*)(Ah + ka) : zz;
            pal[i] = ok ? *(const uint4*)(Al + ka) : zz;
            size_t kb = (size_t)(col0 + lrow[i]) * K + kc * 32 + lseg[i] * 8;
            pbh[i] = *(const uint4*)(Bh + kb);
            pbl[i] = *(const uint4*)(Bl + kb);
        }
    };
    auto STS = [&]() {
        #pragma unroll
        for (int i = 0; i < 2; i++) {
            *(uint4*)&sAh[lrow[i]][lseg[i] * 8] = pah[i];
            *(uint4*)&sAl[lrow[i]][lseg[i] * 8] = pal[i];
            *(uint4*)&sBh[lrow[i]][lseg[i] * 8] = pbh[i];
            *(uint4*)&sBl[lrow[i]][lseg[i] * 8] = pbl[i];
        }
    };

    const uint32_t bAh = s2u(&sAh[0][0]), bAl = s2u(&sAl[0][0]);
    const uint32_t bBh = s2u(&sBh[0][0]), bBl = s2u(&sBl[0][0]);
    // ldmatrix lane addressing (within 16x16 A tile / 16n x 16k B pair)
    const int afr = (lane & 7) + ((lane >> 3) & 1) * 8;   // row within 16
    const int afc = (lane >> 4) * 8;                      // k-col half
    const int bfr = (lane & 7) + (lane >> 4) * 8;         // n row within 16
    const int bfc = ((lane >> 3) & 1) * 8;                // k-col half

    LOADC(0);
    for (int kc = 0; kc < nkc; kc++) {
        __syncthreads();
        STS();
        __syncthreads();
        if (kc + 1 < nkc) LOADC(kc + 1);

        #pragma unroll
        for (int s = 0; s < 2; s++) {
            uint32_t ah[2][4], al[2][4];
            #pragma unroll
            for (int mt = 0; mt < 2; mt++) {
                uint32_t off = ((wm * 32 + mt * 16 + afr) * 40 + s * 16 + afc) * 2;
                ldm4(ah[mt], bAh + off);
                ldm4(al[mt], bAl + off);
            }
            #pragma unroll
            for (int p = 0; p < 4; p++) {
                uint32_t bh4[4], bl4[4];
                uint32_t off = ((wn * 64 + p * 16 + bfr) * 40 + s * 16 + bfc) * 2;
                ldm4(bh4, bBh + off);
                ldm4(bl4, bBl + off);
                #pragma unroll
                for (int mt = 0; mt < 2; mt++) {
                    mma16816(c[mt][2 * p],     ah[mt], bh4 + 0);
                    mma16816(c[mt][2 * p + 1], ah[mt], bh4 + 2);
                    mma16816(c[mt][2 * p],     ah[mt], bl4 + 0);
                    mma16816(c[mt][2 * p + 1], ah[mt], bl4 + 2);
                    mma16816(c[mt][2 * p],     al[mt], bh4 + 0);
                    mma16816(c[mt][2 * p + 1], al[mt], bh4 + 2);
                }
            }
        }
    }

    // epilogue: c-frag (m16n8): c0 (m=lane>>2, n=(lane&3)*2), c1 n+1, c2/c3 m+8
    #pragma unroll
    for (int mt = 0; mt < 2; mt++) {
        #pragma unroll
        for (int nt = 0; nt < 8; nt++) {
            int m = row0 + wm * 32 + mt * 16 + (lane >> 2);
            int nn = col0 + wn * 64 + nt * 8 + (lane & 3) * 2;
            float v0 = c[mt][nt][0], v1 = c[mt][nt][1];
            float v2 = c[mt][nt][2], v3 = c[mt][nt][3];
            if (EPI >= 1) {
                float b0 = bias[nn], b1 = bias[nn + 1];
                v0 += b0; v1 += b1; v2 += b0; v3 += b1;
            }
            if (EPI == 2) { v0 = eluf(v0); v1 = eluf(v1); v2 = eluf(v2); v3 = eluf(v3); }
            if (m < M)     *(float2*)(C + (size_t)m * N + nn)       = make_float2(v0, v1);
            if (m + 8 < M) *(float2*)(C + (size_t)(m + 8) * N + nn) = make_float2(v2, v3);
        }
    }
}

// ---------------------------------------------------------------------------
// CSR build (by destination)
// ---------------------------------------------------------------------------
__global__ void deg_count(const int* __restrict__ ei, int* __restrict__ deg,
                          int E, int Etot)
{
    int e = blockIdx.x * blockDim.x + threadIdx.x;
    if (e >= Etot) return;
    int d = (e < E) ? ei[E + e] : e - E;
    atomicAdd(&deg[d], 1);
}

__global__ __launch_bounds__(256)
void scan_rowptr(const int* __restrict__ deg, int* __restrict__ rowp, int n)
{
    __shared__ int part[256];
    int tid = threadIdx.x;
    int chunk = (n + 255) / 256;
    int lo = tid * chunk;
    int hi = min(lo + chunk, n);
    int s = 0;
    for (int i = lo; i < hi; i++) s += deg[i];
    part[tid] = s;
    __syncthreads();
    for (int off = 1; off < 256; off <<= 1) {
        int v = (tid >= off) ? part[tid - off] : 0;
        __syncthreads();
        part[tid] += v;
        __syncthreads();
    }
    int base = (tid == 0) ? 0 : part[tid - 1];
    for (int i = lo; i < hi; i++) { rowp[i] = base; base += deg[i]; }
    if (tid == 255) rowp[n] = part[255];
}

__global__ void csr_place(const int* __restrict__ ei, const int* __restrict__ rowp,
                          int* __restrict__ wo, int* __restrict__ csrs,
                          int E, int Etot)
{
    int e = blockIdx.x * blockDim.x + threadIdx.x;
    if (e >= Etot) return;
    int s, d;
    if (e < E) { s = ei[e]; d = ei[E + e]; } else { s = d = e - E; }
    int pos = atomicAdd(&wo[d], 1);
    csrs[rowp[d] + pos] = s;
}

// ---------------------------------------------------------------------------
// Attention scores
// ---------------------------------------------------------------------------
__global__ void attn_scores(const float* __restrict__ hw,
                            const float* __restrict__ a_src,
                            const float* __restrict__ a_dst,
                            float* __restrict__ es, float* __restrict__ ed,
                            int n, int H, int C)
{
    int gw = (blockIdx.x * blockDim.x + threadIdx.x) >> 5;
    int lane = threadIdx.x & 31;
    int node = gw / H, h = gw % H;
    if (node >= n) return;
    const float* row = hw + (size_t)node * H * C + h * C;
    const float* as = a_src + h * C;
    const float* ad = a_dst + h * C;
    float ss = 0.f, sd = 0.f;
    for (int c = lane; c < C; c += 32) {
        float v = row[c];
        ss = fmaf(v, as[c], ss);
        sd = fmaf(v, ad[c], sd);
    }
    ss = warpSum(ss);
    sd = warpSum(sd);
    if (lane == 0) { es[node * H + h] = ss; ed[node * H + h] = sd; }
}

// ---------------------------------------------------------------------------
// Fused CSR gather + softmax + bias + LN + ELU (+res / +pool)
// ---------------------------------------------------------------------------
template<int F, int H, bool RES, bool POOL>
__global__ __launch_bounds__(F / 4)
void gather_ln(const float* __restrict__ hw,
               const float* __restrict__ es, const float* __restrict__ ed,
               const int* __restrict__ rowp, const int* __restrict__ csrs,
               const float* __restrict__ bias,
               const float* __restrict__ gam, const float* __restrict__ bet,
               const float* __restrict__ res, float* __restrict__ out,
               const int* __restrict__ batch,
               float* __restrict__ psum, unsigned* __restrict__ pmax)
{
    constexpr int T = F / 4;
    constexpr int C = F / H;
    __shared__ float sh[T / 32 > 1 ? T / 32 : 1];

    const int d = blockIdx.x;
    const int tid = threadIdx.x;
    const int c = tid * 4;
    const int h = c / C;
    const int start = rowp[d];
    const int end = rowp[d + 1];
    const float edh = ed[d * H + h];

    float mx = -1e30f;
    for (int i = start; i < end; i++) {
        int s = csrs[i];
        float l = es[s * H + h] + edh;
        l = l > 0.0f ? l : 0.2f * l;
        mx = fmaxf(mx, l);
    }
    float den = 0.0f;
    for (int i = start; i < end; i++) {
        int s = csrs[i];
        float l = es[s * H + h] + edh;
        l = l > 0.0f ? l : 0.2f * l;
        den += expf(l - mx);
    }
    const float dinv = 1.0f / (den + 1e-16f);
    float4 acc = make_float4(0.f, 0.f, 0.f, 0.f);
    for (int i = start; i < end; i++) {
        int s = csrs[i];
        float l = es[s * H + h] + edh;
        l = l > 0.0f ? l : 0.2f * l;
        float a = expf(l - mx) * dinv;
        float4 v = *(const float4*)(hw + (size_t)s * F + c);
        acc.x = fmaf(v.x, a, acc.x);
        acc.y = fmaf(v.y, a, acc.y);
        acc.z = fmaf(v.z, a, acc.z);
        acc.w = fmaf(v.w, a, acc.w);
    }

    float4 b4 = *(const float4*)(bias + c);
    float v0 = acc.x + b4.x, v1 = acc.y + b4.y, v2 = acc.z + b4.z, v3 = acc.w + b4.w;
    float ssum = blockSum(v0 + v1 + v2 + v3, sh);
    float mu = ssum * (1.0f / F);
    float d0 = v0 - mu, d1 = v1 - mu, d2 = v2 - mu, d3 = v3 - mu;
    float q = blockSum(d0 * d0 + d1 * d1 + d2 * d2 + d3 * d3, sh);
    float inv = rsqrtf(q * (1.0f / F) + 1e-5f);
    float4 g4 = *(const float4*)(gam + c);
    float4 be4 = *(const float4*)(bet + c);
    float y0 = eluf(d0 * inv * g4.x + be4.x);
    float y1 = eluf(d1 * inv * g4.y + be4.y);
    float y2 = eluf(d2 * inv * g4.z + be4.z);
    float y3 = eluf(d3 * inv * g4.w + be4.w);
    if (RES) {
        const float* rp = res + (size_t)d * F + c;
        y0 += rp[0]; y1 += rp[1]; y2 += rp[2]; y3 += rp[3];
    }
    if (POOL) {
        int g = batch[d];
        float* ps = psum + g * 256 + c;
        unsigned* pm = pmax + g * 256 + c;
        atomicAdd(ps + 0, y0); atomicMax(pm + 0, enc_f(y0));
        atomicAdd(ps + 1, y1); atomicMax(pm + 1, enc_f(y1));
        atomicAdd(ps + 2, y2); atomicMax(pm + 2, enc_f(y2));
        atomicAdd(ps + 3, y3); atomicMax(pm + 3, enc_f(y3));
    } else {
        *(float4*)(out + (size_t)d * F + c) = make_float4(y0, y1, y2, y3);
    }
}

// ---------------------------------------------------------------------------
// Pooling count + classifier
// ---------------------------------------------------------------------------
__global__ void pool_cnt(const int* __restrict__ batch, float* __restrict__ pcnt, int n)
{
    int t = blockIdx.x * blockDim.x + threadIdx.x;
    if (t < n) atomicAdd(&pcnt[batch[t]], 1.0f);
}

__global__ __launch_bounds__(128)
void classifier(const float* __restrict__ psum, const unsigned* __restrict__ pmax,
                const float* __restrict__ pcnt,
                const float* __restrict__ w1, const float* __restrict__ b1,
                const float* __restrict__ w2, const float* __restrict__ b2,
                float* __restrict__ out)
{
    int g = blockIdx.x;
    int tid = threadIdx.x;
    __shared__ float p[768];
    __shared__ float r4[4];
    float cnt = fmaxf(pcnt[g], 1.0f);
    for (int i = tid; i < 768; i += 128) {
        float val;
        if (i < 256)      val = psum[g * 256 + i] / cnt;
        else if (i < 512) val = dec_f(pmax[g * 256 + (i - 256)]);
        else              val = psum[g * 256 + (i - 512)];
        p[i] = val;
    }
    __syncthreads();
    float acc = b1[tid];
    for (int k = 0; k < 768; k++) acc = fmaf(p[k], w1[k * 128 + tid], acc);
    float hv = fmaxf(acc, 0.0f) * w2[tid];
    hv = warpSum(hv);
    if ((tid & 31) == 0) r4[tid >> 5] = hv;
    __syncthreads();
    if (tid == 0) out[g] = r4[0] + r4[1] + r4[2] + r4[3] + b2[0];
}

// ---------------------------------------------------------------------------
// Launcher
// ---------------------------------------------------------------------------
extern "C" void kernel_launch(void* const* d_in, const int* in_sizes, int n_in,
                              void* d_out, int out_size)
{
    const float* x        = (const float*)d_in[0];
    const int*   ei       = (const int*)  d_in[1];
    const int*   batch    = (const int*)  d_in[2];
    const float* proj_w   = (const float*)d_in[3];
    const float* proj_b   = (const float*)d_in[4];
    const float* gat1_w   = (const float*)d_in[5];
    const float* att1_src = (const float*)d_in[6];
    const float* att1_dst = (const float*)d_in[7];
    const float* gat1_b   = (const float*)d_in[8];
    const float* ln1_g    = (const float*)d_in[9];
    const float* ln1_b    = (const float*)d_in[10];
    const float* gat2_w   = (const float*)d_in[11];
    const float* att2_src = (const float*)d_in[12];
    const float* att2_dst = (const float*)d_in[13];
    const float* gat2_b   = (const float*)d_in[14];
    const float* ln2_g    = (const float*)d_in[15];
    const float* ln2_b    = (const float*)d_in[16];
    const float* gat3_w   = (const float*)d_in[17];
    const float* att3_src = (const float*)d_in[18];
    const float* att3_dst = (const float*)d_in[19];
    const float* gat3_b   = (const float*)d_in[20];
    const float* ln3_g    = (const float*)d_in[21];
    const float* ln3_b    = (const float*)d_in[22];
    const float* cls1_w   = (const float*)d_in[23];
    const float* cls1_b   = (const float*)d_in[24];
    const float* cls2_w   = (const float*)d_in[25];
    const float* cls2_b   = (const float*)d_in[26];
    float* out = (float*)d_out;

    int n    = in_sizes[2];       // 20000
    int E    = in_sizes[1] / 2;   // 320000
    int Etot = E + n;

    float *h_, *hw, *x1, *x2, *es_, *ed_, *psum, *pcnt;
    __nv_bfloat16 *ah, *al, *bh, *bl;
    int *deg, *rowp, *wo, *csrs;
    unsigned *pmax;
    cudaGetSymbolAddress((void**)&h_,   g_h);
    cudaGetSymbolAddress((void**)&hw,   g_hw);
    cudaGetSymbolAddress((void**)&x1,   g_x1);
    cudaGetSymbolAddress((void**)&x2,   g_x2);
    cudaGetSymbolAddress((void**)&ah,   g_ah);
    cudaGetSymbolAddress((void**)&al,   g_al);
    cudaGetSymbolAddress((void**)&bh,   g_bh);
    cudaGetSymbolAddress((void**)&bl,   g_bl);
    cudaGetSymbolAddress((void**)&es_,  g_es);
    cudaGetSymbolAddress((void**)&ed_,  g_ed);
    cudaGetSymbolAddress((void**)&deg,  g_deg);
    cudaGetSymbolAddress((void**)&rowp, g_rowp);
    cudaGetSymbolAddress((void**)&wo,   g_wo);
    cudaGetSymbolAddress((void**)&csrs, g_csrs);
    cudaGetSymbolAddress((void**)&psum, g_psum);
    cudaGetSymbolAddress((void**)&pmax, g_pmax);
    cudaGetSymbolAddress((void**)&pcnt, g_pcnt);

    int mTiles  = (n + 127) / 128;
    int eBlocks = (Etot + 255) / 256;

    // ---- CSR build ----
    cudaMemsetAsync(deg, 0, (size_t)(n + 1) * sizeof(int), 0);
    cudaMemsetAsync(wo,  0, (size_t)n * sizeof(int), 0);
    deg_count<<<eBlocks, 256>>>(ei, deg, E, Etot);
    scan_rowptr<<<1, 256>>>(deg, rowp, n);
    csr_place<<<eBlocks, 256>>>(ei, rowp, wo, csrs, E, Etot);

    // ---- proj: h = elu(x @ proj_w + proj_b) ----
    split_a<<<(n * 768 / 4 + 255) / 256, 256>>>(x, ah, al, n * 768);
    tsplit_w<<<dim3(768 / 32, 768 / 32), 256>>>(proj_w, bh, bl, 768, 768);
    hmma_gemm<2><<<dim3(768 / 128, mTiles), 256>>>(ah, al, bh, bl, proj_b, h_, n, 768, 768);

    // ---- GAT layer 1 (H=4, F=1024) ----
    split_a<<<(n * 768 / 4 + 255) / 256, 256>>>(h_, ah, al, n * 768);
    tsplit_w<<<dim3(1024 / 32, 768 / 32), 256>>>(gat1_w, bh, bl, 768, 1024);
    hmma_gemm<0><<<dim3(1024 / 128, mTiles), 256>>>(ah, al, bh, bl, nullptr, hw, n, 1024, 768);
    attn_scores<<<(n * 4 + 7) / 8, 256>>>(hw, att1_src, att1_dst, es_, ed_, n, 4, 256);
    gather_ln<1024, 4, false, false><<<n, 256>>>(hw, es_, ed_, rowp, csrs,
        gat1_b, ln1_g, ln1_b, nullptr, x1, nullptr, nullptr, nullptr);

    // ---- GAT layer 2 (H=4, F=1024, residual) ----
    split_a<<<(n * 1024 / 4 + 255) / 256, 256>>>(x1, ah, al, n * 1024);
    tsplit_w<<<dim3(1024 / 32, 1024 / 32), 256>>>(gat2_w, bh, bl, 1024, 1024);
    hmma_gemm<0><<<dim3(1024 / 128, mTiles), 256>>>(ah, al, bh, bl, nullptr, hw, n, 1024, 1024);
    attn_scores<<<(n * 4 + 7) / 8, 256>>>(hw, att2_src, att2_dst, es_, ed_, n, 4, 256);
    gather_ln<1024, 4, true, false><<<n, 256>>>(hw, es_, ed_, rowp, csrs,
        gat2_b, ln2_g, ln2_b, x1, x2, nullptr, nullptr, nullptr);

    // ---- GAT layer 3 (H=1, F=256) + fused pooling ----
    split_a<<<(n * 1024 / 4 + 255) / 256, 256>>>(x2, ah, al, n * 1024);
    tsplit_w<<<dim3(256 / 32, 1024 / 32), 256>>>(gat3_w, bh, bl, 1024, 256);
    hmma_gemm<0><<<dim3(256 / 128, mTiles), 256>>>(ah, al, bh, bl, nullptr, hw, n, 256, 1024);
    attn_scores<<<(n + 7) / 8, 256>>>(hw, att3_src, att3_dst, es_, ed_, n, 1, 256);
    cudaMemsetAsync(psum, 0, (size_t)GMAX * 256 * sizeof(float), 0);
    cudaMemsetAsync(pmax, 0, (size_t)GMAX * 256 * sizeof(unsigned), 0);
    cudaMemsetAsync(pcnt, 0, (size_t)GMAX * sizeof(float), 0);
    pool_cnt<<<(n + 255) / 256, 256>>>(batch, pcnt, n);
    gather_ln<256, 1, false, true><<<n, 64>>>(hw, es_, ed_, rowp, csrs,
        gat3_b, ln3_g, ln3_b, nullptr, nullptr, batch, psum, pmax);

    // ---- Classifier ----
    classifier<<<GMAX, 128>>>(psum, pmax, pcnt, cls1_w, cls1_b, cls2_w, cls2_b, out);
}

// round 9
// speedup vs baseline: 2.8400x; 1.0830x over previous
#include <cuda_runtime.h>
#include <cuda_bf16.h>
#include <math.h>
#include <stdint.h>

// ---------------------------------------------------------------------------
// Problem constants
// ---------------------------------------------------------------------------
#define NMAX   20000
#define EMAX   320000
#define ETOTMX (EMAX + NMAX)
#define GMAX   32

// ---------------------------------------------------------------------------
// Scratch (device globals; no allocations allowed anywhere)
// ---------------------------------------------------------------------------
__device__ float         g_hw  [NMAX * 1024];
__device__ float         g_x1  [NMAX * 1024];
__device__ __nv_bfloat16 g_ah  [NMAX * 1024];
__device__ __nv_bfloat16 g_al  [NMAX * 1024];
__device__ __nv_bfloat16 g_ah2 [NMAX * 1024];
__device__ __nv_bfloat16 g_al2 [NMAX * 1024];
__device__ __nv_bfloat16 g_bh  [1024 * 1024];
__device__ __nv_bfloat16 g_bl  [1024 * 1024];
__device__ float         g_es  [NMAX * 4];
__device__ float         g_ed  [NMAX * 4];
__device__ int           g_deg [NMAX + 1];
__device__ int           g_rowp[NMAX + 1];
__device__ int           g_wo  [NMAX];
__device__ int           g_csrs[ETOTMX];
__device__ float         g_psum[GMAX * 256];
__device__ unsigned      g_pmax[GMAX * 256];
__device__ float         g_pcnt[GMAX];

// ---------------------------------------------------------------------------
// Helpers
// ---------------------------------------------------------------------------
__device__ __forceinline__ unsigned enc_f(float f) {
    unsigned u = __float_as_uint(f);
    return (u & 0x80000000u) ? ~u : (u | 0x80000000u);
}
__device__ __forceinline__ float dec_f(unsigned k) {
    unsigned u = (k & 0x80000000u) ? (k & 0x7fffffffu) : ~k;
    return __uint_as_float(u);
}
__device__ __forceinline__ float warpSum(float v) {
    #pragma unroll
    for (int o = 16; o > 0; o >>= 1) v += __shfl_xor_sync(0xffffffffu, v, o);
    return v;
}
__device__ __forceinline__ float warpMax(float v) {
    #pragma unroll
    for (int o = 16; o > 0; o >>= 1) v = fmaxf(v, __shfl_xor_sync(0xffffffffu, v, o));
    return v;
}
__device__ __forceinline__ float blockSum(float v, float* sh) {
    int lane = threadIdx.x & 31, w = threadIdx.x >> 5;
    int nw = blockDim.x >> 5;
    v = warpSum(v);
    __syncthreads();
    if (lane == 0) sh[w] = v;
    __syncthreads();
    float r = (threadIdx.x < nw) ? sh[threadIdx.x] : 0.0f;
    if (w == 0) {
        r = warpSum(r);
        if (lane == 0) sh[0] = r;
    }
    __syncthreads();
    return sh[0];
}
__device__ __forceinline__ float eluf(float x) { return x > 0.0f ? x : expm1f(x); }

__device__ __forceinline__ uint32_t s2u(const void* p) {
    uint32_t a;
    asm("{ .reg .u64 t; cvta.to.shared.u64 t, %1; cvt.u32.u64 %0, t; }"
        : "=r"(a) : "l"(p));
    return a;
}
__device__ __forceinline__ void ldm4(uint32_t* r, uint32_t addr) {
    asm volatile("ldmatrix.sync.aligned.m8n8.x4.shared.b16 {%0,%1,%2,%3}, [%4];"
                 : "=r"(r[0]), "=r"(r[1]), "=r"(r[2]), "=r"(r[3]) : "r"(addr));
}
__device__ __forceinline__ void mma16816(float* c, const uint32_t* a, const uint32_t* b) {
    asm volatile(
        "mma.sync.aligned.m16n8k16.row.col.f32.bf16.bf16.f32 "
        "{%0,%1,%2,%3}, {%4,%5,%6,%7}, {%8,%9}, {%0,%1,%2,%3};"
        : "+f"(c[0]), "+f"(c[1]), "+f"(c[2]), "+f"(c[3])
        : "r"(a[0]), "r"(a[1]), "r"(a[2]), "r"(a[3]), "r"(b[0]), "r"(b[1]));
}
__device__ __forceinline__ __nv_bfloat162 split_hi2(float a, float b,
                                                    __nv_bfloat162& lo) {
    __nv_bfloat16 h0 = __float2bfloat16(a), h1 = __float2bfloat16(b);
    lo = __nv_bfloat162(__float2bfloat16(a - __bfloat162float(h0)),
                        __float2bfloat16(b - __bfloat162float(h1)));
    return __nv_bfloat162(h0, h1);
}

// ---------------------------------------------------------------------------
// Split A (fp32 -> bf16 hi + bf16 lo residual) — only used for the raw input x
// ---------------------------------------------------------------------------
__global__ void split_a(const float* __restrict__ in,
                        __nv_bfloat16* __restrict__ hi,
                        __nv_bfloat16* __restrict__ lo, int total)
{
    int i = (blockIdx.x * blockDim.x + threadIdx.x) * 4;
    if (i >= total) return;
    float4 v = *(const float4*)(in + i);
    __nv_bfloat162 l01, l23;
    __nv_bfloat162 h01 = split_hi2(v.x, v.y, l01);
    __nv_bfloat162 h23 = split_hi2(v.z, v.w, l23);
    *(__nv_bfloat162*)(hi + i)     = h01;
    *(__nv_bfloat162*)(hi + i + 2) = h23;
    *(__nv_bfloat162*)(lo + i)     = l01;
    *(__nv_bfloat162*)(lo + i + 2) = l23;
}

// ---------------------------------------------------------------------------
// Transpose + split W: W[K,N] fp32 -> Bh,Bl [N,K] bf16
// ---------------------------------------------------------------------------
__global__ __launch_bounds__(256)
void tsplit_w(const float* __restrict__ W,
              __nv_bfloat16* __restrict__ bh, __nv_bfloat16* __restrict__ bl,
              int K, int N)
{
    __shared__ float t[32][33];
    int n0 = blockIdx.x * 32, k0 = blockIdx.y * 32;
    int tx = threadIdx.x & 31, ty = threadIdx.x >> 5;
    #pragma unroll
    for (int r = ty; r < 32; r += 8)
        t[r][tx] = W[(size_t)(k0 + r) * N + n0 + tx];
    __syncthreads();
    #pragma unroll
    for (int r = ty; r < 32; r += 8) {
        float v = t[tx][r];
        __nv_bfloat16 h = __float2bfloat16(v);
        bh[(size_t)(n0 + r) * K + k0 + tx] = h;
        bl[(size_t)(n0 + r) * K + k0 + tx] = __float2bfloat16(v - __bfloat162float(h));
    }
}

// ---------------------------------------------------------------------------
// HMMA GEMM via ldmatrix + mma.sync, bf16 3-split (AhBh + AhBl + AlBh).
// EPI: 0 = f32 out, 2 = bias+ELU f32 out, 3 = bias+ELU, bf16-split out only.
// ---------------------------------------------------------------------------
template<int EPI>
__global__ __launch_bounds__(256)
void hmma_gemm(const __nv_bfloat16* __restrict__ Ah, const __nv_bfloat16* __restrict__ Al,
               const __nv_bfloat16* __restrict__ Bh, const __nv_bfloat16* __restrict__ Bl,
               const float* __restrict__ bias, float* __restrict__ C,
               __nv_bfloat16* __restrict__ Ch, __nv_bfloat16* __restrict__ Cl,
               int M, int N, int K)
{
    __shared__ __nv_bfloat16 sAh[128][40];
    __shared__ __nv_bfloat16 sAl[128][40];
    __shared__ __nv_bfloat16 sBh[128][40];
    __shared__ __nv_bfloat16 sBl[128][40];

    const int tid = threadIdx.x;
    const int lane = tid & 31, wid = tid >> 5;
    const int wm = wid & 3, wn = wid >> 2;
    const int row0 = blockIdx.y * 128, col0 = blockIdx.x * 128;

    float c[2][8][4];
    #pragma unroll
    for (int i = 0; i < 2; i++)
        #pragma unroll
        for (int j = 0; j < 8; j++)
            #pragma unroll
            for (int q = 0; q < 4; q++) c[i][j][q] = 0.0f;

    int lrow[2], lseg[2];
    #pragma unroll
    for (int i = 0; i < 2; i++) { int u = i * 256 + tid; lrow[i] = u >> 2; lseg[i] = u & 3; }

    const int nkc = K >> 5;
    uint4 pah[2], pal[2], pbh[2], pbl[2];
    const uint4 zz = make_uint4(0u, 0u, 0u, 0u);

    auto LOADC = [&](int kc) {
        #pragma unroll
        for (int i = 0; i < 2; i++) {
            int ar = row0 + lrow[i];
            bool ok = ar < M;
            size_t ka = (size_t)ar * K + kc * 32 + lseg[i] * 8;
            pah[i] = ok ? *(const uint4*)(Ah + ka) : zz;
            pal[i] = ok ? *(const uint4*)(Al + ka) : zz;
            size_t kb = (size_t)(col0 + lrow[i]) * K + kc * 32 + lseg[i] * 8;
            pbh[i] = *(const uint4*)(Bh + kb);
            pbl[i] = *(const uint4*)(Bl + kb);
        }
    };
    auto STS = [&]() {
        #pragma unroll
        for (int i = 0; i < 2; i++) {
            *(uint4*)&sAh[lrow[i]][lseg[i] * 8] = pah[i];
            *(uint4*)&sAl[lrow[i]][lseg[i] * 8] = pal[i];
            *(uint4*)&sBh[lrow[i]][lseg[i] * 8] = pbh[i];
            *(uint4*)&sBl[lrow[i]][lseg[i] * 8] = pbl[i];
        }
    };

    const uint32_t bAh = s2u(&sAh[0][0]), bAl = s2u(&sAl[0][0]);
    const uint32_t bBh = s2u(&sBh[0][0]), bBl = s2u(&sBl[0][0]);
    const int afr = (lane & 7) + ((lane >> 3) & 1) * 8;
    const int afc = (lane >> 4) * 8;
    const int bfr = (lane & 7) + (lane >> 4) * 8;
    const int bfc = ((lane >> 3) & 1) * 8;

    LOADC(0);
    for (int kc = 0; kc < nkc; kc++) {
        __syncthreads();
        STS();
        __syncthreads();
        if (kc + 1 < nkc) LOADC(kc + 1);

        #pragma unroll
        for (int s = 0; s < 2; s++) {
            uint32_t ah[2][4], al[2][4];
            #pragma unroll
            for (int mt = 0; mt < 2; mt++) {
                uint32_t off = ((wm * 32 + mt * 16 + afr) * 40 + s * 16 + afc) * 2;
                ldm4(ah[mt], bAh + off);
                ldm4(al[mt], bAl + off);
            }
            #pragma unroll
            for (int p = 0; p < 4; p++) {
                uint32_t bh4[4], bl4[4];
                uint32_t off = ((wn * 64 + p * 16 + bfr) * 40 + s * 16 + bfc) * 2;
                ldm4(bh4, bBh + off);
                ldm4(bl4, bBl + off);
                #pragma unroll
                for (int mt = 0; mt < 2; mt++) {
                    mma16816(c[mt][2 * p],     ah[mt], bh4 + 0);
                    mma16816(c[mt][2 * p + 1], ah[mt], bh4 + 2);
                    mma16816(c[mt][2 * p],     ah[mt], bl4 + 0);
                    mma16816(c[mt][2 * p + 1], ah[mt], bl4 + 2);
                    mma16816(c[mt][2 * p],     al[mt], bh4 + 0);
                    mma16816(c[mt][2 * p + 1], al[mt], bh4 + 2);
                }
            }
        }
    }

    #pragma unroll
    for (int mt = 0; mt < 2; mt++) {
        #pragma unroll
        for (int nt = 0; nt < 8; nt++) {
            int m = row0 + wm * 32 + mt * 16 + (lane >> 2);
            int nn = col0 + wn * 64 + nt * 8 + (lane & 3) * 2;
            float v0 = c[mt][nt][0], v1 = c[mt][nt][1];
            float v2 = c[mt][nt][2], v3 = c[mt][nt][3];
            if (EPI >= 2) {
                float b0 = bias[nn], b1 = bias[nn + 1];
                v0 = eluf(v0 + b0); v1 = eluf(v1 + b1);
                v2 = eluf(v2 + b0); v3 = eluf(v3 + b1);
            }
            if (EPI == 3) {
                __nv_bfloat162 lo;
                if (m < M) {
                    __nv_bfloat162 hi = split_hi2(v0, v1, lo);
                    *(__nv_bfloat162*)(Ch + (size_t)m * N + nn) = hi;
                    *(__nv_bfloat162*)(Cl + (size_t)m * N + nn) = lo;
                }
                if (m + 8 < M) {
                    __nv_bfloat162 hi = split_hi2(v2, v3, lo);
                    *(__nv_bfloat162*)(Ch + (size_t)(m + 8) * N + nn) = hi;
                    *(__nv_bfloat162*)(Cl + (size_t)(m + 8) * N + nn) = lo;
                }
            } else {
                if (m < M)     *(float2*)(C + (size_t)m * N + nn)       = make_float2(v0, v1);
                if (m + 8 < M) *(float2*)(C + (size_t)(m + 8) * N + nn) = make_float2(v2, v3);
            }
        }
    }
}

// ---------------------------------------------------------------------------
// CSR build (by destination)
// ---------------------------------------------------------------------------
__global__ void deg_count(const int* __restrict__ ei, int* __restrict__ deg,
                          int E, int Etot)
{
    int e = blockIdx.x * blockDim.x + threadIdx.x;
    if (e >= Etot) return;
    int d = (e < E) ? ei[E + e] : e - E;
    atomicAdd(&deg[d], 1);
}

__global__ __launch_bounds__(256)
void scan_rowptr(const int* __restrict__ deg, int* __restrict__ rowp, int n)
{
    __shared__ int part[256];
    int tid = threadIdx.x;
    int chunk = (n + 255) / 256;
    int lo = tid * chunk;
    int hi = min(lo + chunk, n);
    int s = 0;
    for (int i = lo; i < hi; i++) s += deg[i];
    part[tid] = s;
    __syncthreads();
    for (int off = 1; off < 256; off <<= 1) {
        int v = (tid >= off) ? part[tid - off] : 0;
        __syncthreads();
        part[tid] += v;
        __syncthreads();
    }
    int base = (tid == 0) ? 0 : part[tid - 1];
    for (int i = lo; i < hi; i++) { rowp[i] = base; base += deg[i]; }
    if (tid == 255) rowp[n] = part[255];
}

__global__ void csr_place(const int* __restrict__ ei, const int* __restrict__ rowp,
                          int* __restrict__ wo, int* __restrict__ csrs,
                          int E, int Etot)
{
    int e = blockIdx.x * blockDim.x + threadIdx.x;
    if (e >= Etot) return;
    int s, d;
    if (e < E) { s = ei[e]; d = ei[E + e]; } else { s = d = e - E; }
    int pos = atomicAdd(&wo[d], 1);
    csrs[rowp[d] + pos] = s;
}

// ---------------------------------------------------------------------------
// Attention scores
// ---------------------------------------------------------------------------
__global__ void attn_scores(const float* __restrict__ hw,
                            const float* __restrict__ a_src,
                            const float* __restrict__ a_dst,
                            float* __restrict__ es, float* __restrict__ ed,
                            int n, int H, int C)
{
    int gw = (blockIdx.x * blockDim.x + threadIdx.x) >> 5;
    int lane = threadIdx.x & 31;
    int node = gw / H, h = gw % H;
    if (node >= n) return;
    const float* row = hw + (size_t)node * H * C + h * C;
    const float* as = a_src + h * C;
    const float* ad = a_dst + h * C;
    float ss = 0.f, sd = 0.f;
    for (int c = lane; c < C; c += 32) {
        float v = row[c];
        ss = fmaf(v, as[c], ss);
        sd = fmaf(v, ad[c], sd);
    }
    ss = warpSum(ss);
    sd = warpSum(sd);
    if (lane == 0) { es[node * H + h] = ss; ed[node * H + h] = sd; }
}

// ---------------------------------------------------------------------------
// Fused CSR gather + cooperative softmax + bias + LN + ELU (+res) + out.
// OUT_MODE: 0 = f32 only, 1 = f32 + bf16 split, 2 = bf16 split only, 3 = pool.
// Block = F/4 threads; thread handles 4 consecutive features (head h = c/C).
// Softmax stats computed once per (node,head) by the 64-thread head-group;
// alphas computed once per (edge,head) into smem chunks.
// ---------------------------------------------------------------------------
template<int F, int H, bool RES, int OUT_MODE>
__global__ __launch_bounds__(F / 4)
void gather_ln(const float* __restrict__ hw,
               const float* __restrict__ es, const float* __restrict__ ed,
               const int* __restrict__ rowp, const int* __restrict__ csrs,
               const float* __restrict__ bias,
               const float* __restrict__ gam, const float* __restrict__ bet,
               const float* __restrict__ res, float* __restrict__ out,
               __nv_bfloat16* __restrict__ outh, __nv_bfloat16* __restrict__ outl,
               const int* __restrict__ batch,
               float* __restrict__ psum, unsigned* __restrict__ pmax)
{
    constexpr int T  = F / 4;          // threads
    constexpr int C  = F / H;          // feats per head
    constexpr int GT = T / H;          // threads per head group (64)
    constexpr int GW = GT / 32;        // warps per head group (2)
    constexpr int CH = 64;             // edge chunk
    __shared__ float s_part[T / 32];
    __shared__ float s_mx[H], s_dinv[H];
    __shared__ float s_al[CH * H];

    const int d = blockIdx.x;
    const int tid = threadIdx.x;
    const int lane = tid & 31, wid = tid >> 5;
    const int c = tid * 4;
    const int h = tid / GT;
    const int sub = tid - h * GT;
    const int start = rowp[d];
    const int end = rowp[d + 1];
    const float edh = ed[d * H + h];

    // phase 1: group max
    float mx = -1e30f;
    for (int i = start + sub; i < end; i += GT) {
        float l = es[csrs[i] * H + h] + edh;
        l = l > 0.0f ? l : 0.2f * l;
        mx = fmaxf(mx, l);
    }
    mx = warpMax(mx);
    if (lane == 0) s_part[wid] = mx;
    __syncthreads();
    mx = s_part[h * GW];
    #pragma unroll
    for (int w = 1; w < GW; w++) mx = fmaxf(mx, s_part[h * GW + w]);
    __syncthreads();

    // phase 2: group denominator
    float den = 0.0f;
    for (int i = start + sub; i < end; i += GT) {
        float l = es[csrs[i] * H + h] + edh;
        l = l > 0.0f ? l : 0.2f * l;
        den += expf(l - mx);
    }
    den = warpSum(den);
    if (lane == 0) s_part[wid] = den;
    __syncthreads();
    den = s_part[h * GW];
    #pragma unroll
    for (int w = 1; w < GW; w++) den += s_part[h * GW + w];
    if (sub == 0) { s_mx[h] = mx; s_dinv[h] = 1.0f / (den + 1e-16f); }
    __syncthreads();

    // phase 3: chunked cooperative alpha + feature gather
    float4 acc = make_float4(0.f, 0.f, 0.f, 0.f);
    for (int base = start; base < end; base += CH) {
        const int cnt = min(CH, end - base);
        for (int j = tid; j < cnt * H; j += T) {
            int ee = j / H, hh = j - ee * H;
            int s = csrs[base + ee];
            float l = es[s * H + hh] + ed[d * H + hh];
            l = l > 0.0f ? l : 0.2f * l;
            s_al[ee * H + hh] = expf(l - s_mx[hh]) * s_dinv[hh];
        }
        __syncthreads();
        for (int i = 0; i < cnt; i++) {
            int s = csrs[base + i];
            float a = s_al[i * H + h];
            float4 v = *(const float4*)(hw + (size_t)s * F + c);
            acc.x = fmaf(v.x, a, acc.x);
            acc.y = fmaf(v.y, a, acc.y);
            acc.z = fmaf(v.z, a, acc.z);
            acc.w = fmaf(v.w, a, acc.w);
        }
        __syncthreads();
    }

    // bias + LayerNorm + ELU (+ residual)
    float4 b4 = *(const float4*)(bias + c);
    float v0 = acc.x + b4.x, v1 = acc.y + b4.y, v2 = acc.z + b4.z, v3 = acc.w + b4.w;
    float ssum = blockSum(v0 + v1 + v2 + v3, s_part);
    float mu = ssum * (1.0f / F);
    float d0 = v0 - mu, d1 = v1 - mu, d2 = v2 - mu, d3 = v3 - mu;
    float q = blockSum(d0 * d0 + d1 * d1 + d2 * d2 + d3 * d3, s_part);
    float inv = rsqrtf(q * (1.0f / F) + 1e-5f);
    float4 g4 = *(const float4*)(gam + c);
    float4 be4 = *(const float4*)(bet + c);
    float y0 = eluf(d0 * inv * g4.x + be4.x);
    float y1 = eluf(d1 * inv * g4.y + be4.y);
    float y2 = eluf(d2 * inv * g4.z + be4.z);
    float y3 = eluf(d3 * inv * g4.w + be4.w);
    if (RES) {
        const float* rp = res + (size_t)d * F + c;
        y0 += rp[0]; y1 += rp[1]; y2 += rp[2]; y3 += rp[3];
    }

    if (OUT_MODE == 3) {
        int g = batch[d];
        float* ps = psum + g * 256 + c;
        unsigned* pm = pmax + g * 256 + c;
        atomicAdd(ps + 0, y0); atomicMax(pm + 0, enc_f(y0));
        atomicAdd(ps + 1, y1); atomicMax(pm + 1, enc_f(y1));
        atomicAdd(ps + 2, y2); atomicMax(pm + 2, enc_f(y2));
        atomicAdd(ps + 3, y3); atomicMax(pm + 3, enc_f(y3));
    } else {
        if (OUT_MODE <= 1)
            *(float4*)(out + (size_t)d * F + c) = make_float4(y0, y1, y2, y3);
        if (OUT_MODE >= 1) {
            __nv_bfloat162 lo01, lo23;
            __nv_bfloat162 hi01 = split_hi2(y0, y1, lo01);
            __nv_bfloat162 hi23 = split_hi2(y2, y3, lo23);
            *(__nv_bfloat162*)(outh + (size_t)d * F + c)     = hi01;
            *(__nv_bfloat162*)(outh + (size_t)d * F + c + 2) = hi23;
            *(__nv_bfloat162*)(outl + (size_t)d * F + c)     = lo01;
            *(__nv_bfloat162*)(outl + (size_t)d * F + c + 2) = lo23;
        }
    }
}

// ---------------------------------------------------------------------------
// Pooling count + classifier
// ---------------------------------------------------------------------------
__global__ void pool_cnt(const int* __restrict__ batch, float* __restrict__ pcnt, int n)
{
    int t = blockIdx.x * blockDim.x + threadIdx.x;
    if (t < n) atomicAdd(&pcnt[batch[t]], 1.0f);
}

__global__ __launch_bounds__(128)
void classifier(const float* __restrict__ psum, const unsigned* __restrict__ pmax,
                const float* __restrict__ pcnt,
                const float* __restrict__ w1, const float* __restrict__ b1,
                const float* __restrict__ w2, const float* __restrict__ b2,
                float* __restrict__ out)
{
    int g = blockIdx.x;
    int tid = threadIdx.x;
    __shared__ float p[768];
    __shared__ float r4[4];
    float cnt = fmaxf(pcnt[g], 1.0f);
    for (int i = tid; i < 768; i += 128) {
        float val;
        if (i < 256)      val = psum[g * 256 + i] / cnt;
        else if (i < 512) val = dec_f(pmax[g * 256 + (i - 256)]);
        else              val = psum[g * 256 + (i - 512)];
        p[i] = val;
    }
    __syncthreads();
    float acc = b1[tid];
    for (int k = 0; k < 768; k++) acc = fmaf(p[k], w1[k * 128 + tid], acc);
    float hv = fmaxf(acc, 0.0f) * w2[tid];
    hv = warpSum(hv);
    if ((tid & 31) == 0) r4[tid >> 5] = hv;
    __syncthreads();
    if (tid == 0) out[g] = r4[0] + r4[1] + r4[2] + r4[3] + b2[0];
}

// ---------------------------------------------------------------------------
// Launcher
// ---------------------------------------------------------------------------
extern "C" void kernel_launch(void* const* d_in, const int* in_sizes, int n_in,
                              void* d_out, int out_size)
{
    const float* x        = (const float*)d_in[0];
    const int*   ei       = (const int*)  d_in[1];
    const int*   batch    = (const int*)  d_in[2];
    const float* proj_w   = (const float*)d_in[3];
    const float* proj_b   = (const float*)d_in[4];
    const float* gat1_w   = (const float*)d_in[5];
    const float* att1_src = (const float*)d_in[6];
    const float* att1_dst = (const float*)d_in[7];
    const float* gat1_b   = (const float*)d_in[8];
    const float* ln1_g    = (const float*)d_in[9];
    const float* ln1_b    = (const float*)d_in[10];
    const float* gat2_w   = (const float*)d_in[11];
    const float* att2_src = (const float*)d_in[12];
    const float* att2_dst = (const float*)d_in[13];
    const float* gat2_b   = (const float*)d_in[14];
    const float* ln2_g    = (const float*)d_in[15];
    const float* ln2_b    = (const float*)d_in[16];
    const float* gat3_w   = (const float*)d_in[17];
    const float* att3_src = (const float*)d_in[18];
    const float* att3_dst = (const float*)d_in[19];
    const float* gat3_b   = (const float*)d_in[20];
    const float* ln3_g    = (const float*)d_in[21];
    const float* ln3_b    = (const float*)d_in[22];
    const float* cls1_w   = (const float*)d_in[23];
    const float* cls1_b   = (const float*)d_in[24];
    const float* cls2_w   = (const float*)d_in[25];
    const float* cls2_b   = (const float*)d_in[26];
    float* out = (float*)d_out;

    int n    = in_sizes[2];       // 20000
    int E    = in_sizes[1] / 2;   // 320000
    int Etot = E + n;

    float *hw, *x1, *es_, *ed_, *psum, *pcnt;
    __nv_bfloat16 *ah, *al, *ah2, *al2, *bh, *bl;
    int *deg, *rowp, *wo, *csrs;
    unsigned *pmax;
    cudaGetSymbolAddress((void**)&hw,   g_hw);
    cudaGetSymbolAddress((void**)&x1,   g_x1);
    cudaGetSymbolAddress((void**)&ah,   g_ah);
    cudaGetSymbolAddress((void**)&al,   g_al);
    cudaGetSymbolAddress((void**)&ah2,  g_ah2);
    cudaGetSymbolAddress((void**)&al2,  g_al2);
    cudaGetSymbolAddress((void**)&bh,   g_bh);
    cudaGetSymbolAddress((void**)&bl,   g_bl);
    cudaGetSymbolAddress((void**)&es_,  g_es);
    cudaGetSymbolAddress((void**)&ed_,  g_ed);
    cudaGetSymbolAddress((void**)&deg,  g_deg);
    cudaGetSymbolAddress((void**)&rowp, g_rowp);
    cudaGetSymbolAddress((void**)&wo,   g_wo);
    cudaGetSymbolAddress((void**)&csrs, g_csrs);
    cudaGetSymbolAddress((void**)&psum, g_psum);
    cudaGetSymbolAddress((void**)&pmax, g_pmax);
    cudaGetSymbolAddress((void**)&pcnt, g_pcnt);

    int mTiles  = (n + 127) / 128;
    int eBlocks = (Etot + 255) / 256;

    // ---- CSR build ----
    cudaMemsetAsync(deg, 0, (size_t)(n + 1) * sizeof(int), 0);
    cudaMemsetAsync(wo,  0, (size_t)n * sizeof(int), 0);
    deg_count<<<eBlocks, 256>>>(ei, deg, E, Etot);
    scan_rowptr<<<1, 256>>>(deg, rowp, n);
    csr_place<<<eBlocks, 256>>>(ei, rowp, wo, csrs, E, Etot);

    // ---- proj: (ah2,al2) = split(elu(x @ proj_w + proj_b)) ----
    split_a<<<(n * 768 / 4 + 255) / 256, 256>>>(x, ah, al, n * 768);
    tsplit_w<<<dim3(768 / 32, 768 / 32), 256>>>(proj_w, bh, bl, 768, 768);
    hmma_gemm<3><<<dim3(768 / 128, mTiles), 256>>>(ah, al, bh, bl, proj_b,
        nullptr, ah2, al2, n, 768, 768);

    // ---- GAT layer 1 (H=4, F=1024): out x1 f32 + (ah,al) split ----
    tsplit_w<<<dim3(1024 / 32, 768 / 32), 256>>>(gat1_w, bh, bl, 768, 1024);
    hmma_gemm<0><<<dim3(1024 / 128, mTiles), 256>>>(ah2, al2, bh, bl, nullptr,
        hw, nullptr, nullptr, n, 1024, 768);
    attn_scores<<<(n * 4 + 7) / 8, 256>>>(hw, att1_src, att1_dst, es_, ed_, n, 4, 256);
    gather_ln<1024, 4, false, 1><<<n, 256>>>(hw, es_, ed_, rowp, csrs,
        gat1_b, ln1_g, ln1_b, nullptr, x1, ah, al, nullptr, nullptr, nullptr);

    // ---- GAT layer 2 (H=4, F=1024, residual): out (ah2,al2) split only ----
    tsplit_w<<<dim3(1024 / 32, 1024 / 32), 256>>>(gat2_w, bh, bl, 1024, 1024);
    hmma_gemm<0><<<dim3(1024 / 128, mTiles), 256>>>(ah, al, bh, bl, nullptr,
        hw, nullptr, nullptr, n, 1024, 1024);
    attn_scores<<<(n * 4 + 7) / 8, 256>>>(hw, att2_src, att2_dst, es_, ed_, n, 4, 256);
    gather_ln<1024, 4, true, 2><<<n, 256>>>(hw, es_, ed_, rowp, csrs,
        gat2_b, ln2_g, ln2_b, x1, nullptr, ah2, al2, nullptr, nullptr, nullptr);

    // ---- GAT layer 3 (H=1, F=256) + fused pooling ----
    tsplit_w<<<dim3(256 / 32, 1024 / 32), 256>>>(gat3_w, bh, bl, 1024, 256);
    hmma_gemm<0><<<dim3(256 / 128, mTiles), 256>>>(ah2, al2, bh, bl, nullptr,
        hw, nullptr, nullptr, n, 256, 1024);
    attn_scores<<<(n + 7) / 8, 256>>>(hw, att3_src, att3_dst, es_, ed_, n, 1, 256);
    cudaMemsetAsync(psum, 0, (size_t)GMAX * 256 * sizeof(float), 0);
    cudaMemsetAsync(pmax, 0, (size_t)GMAX * 256 * sizeof(unsigned), 0);
    cudaMemsetAsync(pcnt, 0, (size_t)GMAX * sizeof(float), 0);
    pool_cnt<<<(n + 255) / 256, 256>>>(batch, pcnt, n);
    gather_ln<256, 1, false, 3><<<n, 64>>>(hw, es_, ed_, rowp, csrs,
        gat3_b, ln3_g, ln3_b, nullptr, nullptr, nullptr, nullptr, batch, psum, pmax);

    // ---- Classifier ----
    classifier<<<GMAX, 128>>>(psum, pmax, pcnt, cls1_w, cls1_b, cls2_w, cls2_b, out);
}